// round 8
// baseline (speedup 1.0000x reference)
#include <cuda_runtime.h>
#include <cuda_bf16.h>
#include <mma.h>
#include <cstdint>

using namespace nvcuda;

#define N_TOK   65536
#define K_IN    64
#define E_DIM   512
#define V_SIZE  2048
#define CAND_CAP 16
#define NCH     2                 // codebook chunks (blockIdx.y)
#define VC      (V_SIZE / NCH)    // 1024 codes per CTA

typedef unsigned long long ull;

// ---- scratch (device globals: no runtime allocation allowed) ----
__device__ float           g_zp [(size_t)N_TOK * E_DIM];
__device__ __nv_bfloat16   g_zpH[(size_t)N_TOK * E_DIM];
__device__ __nv_bfloat16   g_ebH[(size_t)V_SIZE * E_DIM];
__device__ float           g_C  [N_TOK];
__device__ float           g_e2 [V_SIZE];
__device__ int             g_tok[N_TOK];
__device__ float           g_P  [(size_t)V_SIZE * 64];
__device__ int             g_cand[(size_t)N_TOK * (NCH * CAND_CAP)];
__device__ int             g_nc  [NCH][N_TOK];      // -1 = overflow

// ---- packed fp32x2 helpers ----
__device__ __forceinline__ ull fma2(ull a, ull b, ull c) {
    ull d; asm("fma.rn.f32x2 %0, %1, %2, %3;" : "=l"(d) : "l"(a), "l"(b), "l"(c)); return d;
}
__device__ __forceinline__ ull dup2(float x) {
    ull d; asm("mov.b64 %0, {%1, %1};" : "=l"(d) : "f"(x)); return d;
}
__device__ __forceinline__ ull pack2(float x, float y) {
    ull d; asm("mov.b64 %0, {%1, %2};" : "=l"(d) : "f"(x), "f"(y)); return d;
}
__device__ __forceinline__ float2 unpack2(ull v) {
    float2 r; asm("mov.b64 {%0, %1}, %2;" : "=f"(r.x), "=f"(r.y) : "l"(v)); return r;
}

// ============================================================
// Kernel 0: e2 + bf16 copy of emb
// ============================================================
__global__ void e2_kernel(const float* __restrict__ emb) {
    int v = blockIdx.x;
    const float* row = emb + (size_t)v * E_DIM;
    float s = 0.f;
    for (int k = threadIdx.x; k < E_DIM; k += 128) {
        float x = row[k];
        g_ebH[(size_t)v * E_DIM + k] = __float2bfloat16(x);
        s = fmaf(x, x, s);
    }
    for (int off = 16; off > 0; off >>= 1)
        s += __shfl_down_sync(0xffffffffu, s, off);
    __shared__ float ws[4];
    int lane = threadIdx.x & 31, warp = threadIdx.x >> 5;
    if (lane == 0) ws[warp] = s;
    __syncthreads();
    if (threadIdx.x == 0)
        g_e2[v] = ws[0] + ws[1] + ws[2] + ws[3];
}

// ============================================================
// Kernel 1: zp = z @ pre_W + pre_b (FFMA2), C, bf16 copy
// ============================================================
__global__ __launch_bounds__(128) void pre_kernel(
    const float* __restrict__ z, const float* __restrict__ W,
    const float* __restrict__ b)
{
    int n = blockIdx.x;
    __shared__ float zs[K_IN];
    if (threadIdx.x < K_IN) zs[threadIdx.x] = z[(size_t)n * K_IN + threadIdx.x];
    __syncthreads();

    int j0 = threadIdx.x * 4;
    float4 b4 = *(const float4*)&b[j0];
    ull acc0 = pack2(b4.x, b4.y);
    ull acc1 = pack2(b4.z, b4.w);

    #pragma unroll 16
    for (int k = 0; k < K_IN; k++) {
        ull zk = dup2(zs[k]);
        float4 w = *(const float4*)&W[(size_t)k * E_DIM + j0];
        acc0 = fma2(zk, pack2(w.x, w.y), acc0);
        acc1 = fma2(zk, pack2(w.z, w.w), acc1);
    }

    float2 p0 = unpack2(acc0), p1 = unpack2(acc1);
    float4 r; r.x = p0.x; r.y = p0.y; r.z = p1.x; r.w = p1.y;
    *(float4*)&g_zp[(size_t)n * E_DIM + j0] = r;

    __nv_bfloat162 h0 = __floats2bfloat162_rn(r.x, r.y);
    __nv_bfloat162 h1 = __floats2bfloat162_rn(r.z, r.w);
    *(__nv_bfloat162*)&g_zpH[(size_t)n * E_DIM + j0]     = h0;
    *(__nv_bfloat162*)&g_zpH[(size_t)n * E_DIM + j0 + 2] = h1;

    float s = r.x * r.x;
    s = fmaf(r.y, r.y, s);
    s = fmaf(r.z, r.z, s);
    s = fmaf(r.w, r.w, s);
    for (int off = 16; off > 0; off >>= 1)
        s += __shfl_down_sync(0xffffffffu, s, off);
    __shared__ float ws[4];
    int lane = threadIdx.x & 31, warp = threadIdx.x >> 5;
    if (lane == 0) ws[warp] = s;
    __syncthreads();
    if (threadIdx.x == 0)
        g_C[n] = ws[0] + ws[1] + ws[2] + ws[3];
}

// ============================================================
// Kernel 2: WMMA bf16 filter, 512 threads (16 warps, 4x4 grid,
// 32x32 warp tile), codebook split by blockIdx.y (1024 codes).
// A resident in smem; B double-buffered 128x32 chunks; 1 bar
// per chunk; per-vtile epilogue builds candidate lists (2*eps
// bound -> superset of exact argmin; validated rel_err 0.0).
// ============================================================
#define FM 128
#define FN 128
#define A_LDM 520
#define B_LDM 40
#define D_LDM 132
#define N_VT (VC / FN)           // 8 vtiles per CTA
#define N_KC (E_DIM / 32)        // 16 k-chunks per vtile
#define N_CH (N_VT * N_KC)       // 128 chunks

#define OFF_A  0
#define OFF_B  (FM * A_LDM * 2)                    // 133120
#define OFF_D  (OFF_B + 2 * FN * B_LDM * 2)        // 153600
#define OFF_E2 (OFF_D + FM * D_LDM * 4)            // 221184
#define FIL_SMEM (OFF_E2 + FN * 4)                 // 221696

__global__ __launch_bounds__(512, 1) void filter_kernel()
{
    extern __shared__ unsigned char smem[];
    __nv_bfloat16* sA = (__nv_bfloat16*)(smem + OFF_A);
    __nv_bfloat16* sB = (__nv_bfloat16*)(smem + OFF_B);
    float*         sD = (float*)(smem + OFF_D);
    float*        sE2 = (float*)(smem + OFF_E2);

    int tid = threadIdx.x;
    int w   = tid >> 5;
    int wm  = w & 3;          // warp row block (32 rows)
    int wn  = w >> 2;         // warp col block (32 cols)
    int m0  = blockIdx.x * FM;
    int chunkId = blockIdx.y;
    int vc  = chunkId * VC;

    // ---- load A block once: 128 rows x 512 k bf16 ----
    #pragma unroll
    for (int i = 0; i < 16; i++) {
        int idx = tid + 512 * i;
        int row = idx >> 6, c16 = idx & 63;
        uint4 v = *(const uint4*)(g_zpH + (size_t)(m0 + row) * E_DIM + c16 * 8);
        *(uint4*)((unsigned char*)sA + row * (A_LDM * 2) + c16 * 16) = v;
    }

    // ---- B chunk helpers: 128 codes x 32 k = 512 uint4 (1/thread) ----
    int bRow = tid >> 2, bQ = tid & 3;
    uint4 pB;
    #define LOADB(cc) do {                                                   \
        int _v  = (cc) >> 4, _kc = (cc) & 15;                                \
        pB = *(const uint4*)(g_ebH +                                         \
             (size_t)(vc + _v * FN + bRow) * E_DIM + _kc * 32 + bQ * 8);     \
    } while (0)
    #define STSB(bf) do {                                                    \
        *(uint4*)((unsigned char*)sB + (bf) * (FN * B_LDM * 2)               \
                  + bRow * (B_LDM * 2) + bQ * 16) = pB;                      \
    } while (0)

    // ---- per-row candidate state (tid < 128 owns row m0+tid) ----
    float Ci = 0.f, thr = 0.f;
    if (tid < FM) {
        Ci  = g_C[m0 + tid];
        thr = sqrtf(Ci) * (0.01105f * 0.015625f) + 1e-4f;
    }
    float bd = 3.4e38f, bthr = 3.4e38f;
    float cdv[CAND_CAP];
    int   cvv[CAND_CAP];
    int   cnt = 0;
    bool  bad = false;

    wmma::fragment<wmma::accumulator, 16, 16, 16, float> cf[2][2];

    LOADB(0);
    STSB(0);
    LOADB(1);
    __syncthreads();

    #pragma unroll 1
    for (int c = 0; c < N_CH; c++) {
        int buf = c & 1;
        int kc  = c & 15;

        if (c + 1 < N_CH) {
            STSB(buf ^ 1);
            int nx = (c + 2 < N_CH) ? c + 2 : N_CH - 1;
            LOADB(nx);
        }

        if (kc == 0) {
            #pragma unroll
            for (int i = 0; i < 2; i++)
                #pragma unroll
                for (int j = 0; j < 2; j++)
                    wmma::fill_fragment(cf[i][j], 0.0f);
        }

        int ks0 = kc * 32;
        #pragma unroll
        for (int ks = 0; ks < 32; ks += 16) {
            wmma::fragment<wmma::matrix_a, 16, 16, 16, __nv_bfloat16, wmma::row_major> af[2];
            wmma::fragment<wmma::matrix_b, 16, 16, 16, __nv_bfloat16, wmma::col_major> bfr[2];
            #pragma unroll
            for (int i = 0; i < 2; i++)
                wmma::load_matrix_sync(af[i],
                    sA + (size_t)(wm * 32 + i * 16) * A_LDM + ks0 + ks, A_LDM);
            #pragma unroll
            for (int j = 0; j < 2; j++)
                wmma::load_matrix_sync(bfr[j],
                    sB + buf * (FN * B_LDM) + (size_t)(wn * 32 + j * 16) * B_LDM + ks, B_LDM);
            #pragma unroll
            for (int i = 0; i < 2; i++)
                #pragma unroll
                for (int j = 0; j < 2; j++)
                    wmma::mma_sync(cf[i][j], af[i], bfr[j], cf[i][j]);
        }

        __syncthreads();

        if (kc == 15) {
            int vt = c >> 4;
            #pragma unroll
            for (int i = 0; i < 2; i++)
                #pragma unroll
                for (int j = 0; j < 2; j++)
                    wmma::store_matrix_sync(
                        sD + (size_t)(wm * 32 + i * 16) * D_LDM + wn * 32 + j * 16,
                        cf[i][j], D_LDM, wmma::mem_row_major);
            if (tid < FN) sE2[tid] = g_e2[vc + vt * FN + tid];
            __syncthreads();

            if (tid < FM) {
                const float* drow = sD + (size_t)tid * D_LDM;
                #pragma unroll 1
                for (int cb = 0; cb < FN / 4; cb++) {
                    float4 d4 = *(const float4*)(drow + cb * 4);
                    float dv[4] = {d4.x, d4.y, d4.z, d4.w};
                    #pragma unroll
                    for (int q = 0; q < 4; q++) {
                        int vcode = vc + vt * FN + cb * 4 + q;
                        float d = fmaf(-2.0f, dv[q], Ci + sE2[cb * 4 + q]);
                        if (d < bd) { bd = d; bthr = bd + thr; }
                        if (d <= bthr) {
                            if (cnt == CAND_CAP) {
                                int jj = 0;
                                for (int i2 = 0; i2 < CAND_CAP; i2++)
                                    if (cdv[i2] <= bthr) { cdv[jj] = cdv[i2]; cvv[jj] = cvv[i2]; jj++; }
                                cnt = jj;
                            }
                            if (cnt == CAND_CAP) bad = true;
                            else { cdv[cnt] = d; cvv[cnt] = vcode; cnt++; }
                        }
                    }
                }
            }
            __syncthreads();
        }
    }

    if (tid < FM) {
        int n = m0 + tid;
        int jj = 0;
        for (int i2 = 0; i2 < cnt; i2++)
            if (cdv[i2] <= bthr) { cvv[jj] = cvv[i2]; jj++; }
        g_nc[chunkId][n] = bad ? -1 : jj;
        int* dst = g_cand + (size_t)n * (NCH * CAND_CAP) + chunkId * CAND_CAP;
        for (int i2 = 0; i2 < jj; i2++) dst[i2] = cvv[i2];
    }
    #undef LOADB
    #undef STSB
}

// ============================================================
// Kernel 3: exact rescore; lanes 0-15 take chunk0 list, lanes
// 16-31 chunk1 list. Sequential-k fp32 chain (bitwise-proven);
// first-index min tiebreak. Overflow -> exact full scan.
// ============================================================
__global__ __launch_bounds__(256) void rescore_kernel(
    const float* __restrict__ emb, float* __restrict__ out_tok)
{
    int n    = blockIdx.x * 8 + (threadIdx.x >> 5);
    int lane = threadIdx.x & 31;
    int nc0  = g_nc[0][n];
    int nc1  = g_nc[1][n];

    const float* zr = g_zp + (size_t)n * E_DIM;
    float bdv = 3.4e38f;
    int   bvi = 0x7fffffff;

    if (nc0 >= 0 && nc1 >= 0) {
        int v = -1;
        if (lane < 16) { if (lane < nc0) v = g_cand[(size_t)n * 32 + lane]; }
        else           { if (lane - 16 < nc1) v = g_cand[(size_t)n * 32 + 16 + (lane - 16)]; }
        if (v >= 0) {
            const float* er = emb + (size_t)v * E_DIM;
            float dot = 0.f;
            #pragma unroll 8
            for (int k = 0; k < E_DIM; k += 4) {
                float4 a = *(const float4*)(zr + k);
                float4 bb = *(const float4*)(er + k);
                dot = fmaf(a.x, bb.x, dot);
                dot = fmaf(a.y, bb.y, dot);
                dot = fmaf(a.z, bb.z, dot);
                dot = fmaf(a.w, bb.w, dot);
            }
            bdv = fmaf(-2.0f, dot, g_C[n] + g_e2[v]);
            bvi = v;
        }
    } else {
        for (int v = lane; v < V_SIZE; v += 32) {
            const float* er = emb + (size_t)v * E_DIM;
            float dot = 0.f;
            #pragma unroll 8
            for (int k = 0; k < E_DIM; k += 4) {
                float4 a = *(const float4*)(zr + k);
                float4 bb = *(const float4*)(er + k);
                dot = fmaf(a.x, bb.x, dot);
                dot = fmaf(a.y, bb.y, dot);
                dot = fmaf(a.z, bb.z, dot);
                dot = fmaf(a.w, bb.w, dot);
            }
            float d = fmaf(-2.0f, dot, g_C[n] + g_e2[v]);
            if (d < bdv || (d == bdv && v < bvi)) { bdv = d; bvi = v; }
        }
    }

    #pragma unroll
    for (int off = 16; off > 0; off >>= 1) {
        float od = __shfl_xor_sync(0xffffffffu, bdv, off);
        int   ov = __shfl_xor_sync(0xffffffffu, bvi, off);
        if (od < bdv || (od == bdv && ov < bvi)) { bdv = od; bvi = ov; }
    }
    if (lane == 0) {
        g_tok[n] = bvi;
        out_tok[n] = (float)bvi;
    }
}

// ============================================================
// Kernel 4: P = emb @ post_W + post_b   [2048, 64]
// ============================================================
#define BM 64
#define BK 32

__global__ __launch_bounds__(256) void pmat_kernel(
    const float* __restrict__ emb, const float* __restrict__ W,
    const float* __restrict__ b)
{
    __shared__ float As2[BK][BM + 4];
    __shared__ float Bs2[BK][64 + 4];

    int m0  = blockIdx.x * BM;
    int tid = threadIdx.x;
    int tx  = tid & 15;
    int ty  = tid >> 4;

    float acc[4][4];
    #pragma unroll
    for (int i = 0; i < 4; i++)
        #pragma unroll
        for (int jj = 0; jj < 4; jj++) acc[i][jj] = 0.f;

    for (int k0 = 0; k0 < E_DIM; k0 += BK) {
        #pragma unroll
        for (int i = 0; i < 8; i++) {
            int idx = tid + 256 * i;
            int m = idx >> 5, kk = idx & 31;
            As2[kk][m] = emb[(size_t)(m0 + m) * E_DIM + k0 + kk];
        }
        #pragma unroll
        for (int i = 0; i < 8; i++) {
            int idx = tid + 256 * i;
            int kk = idx >> 6, jj = idx & 63;
            Bs2[kk][jj] = W[(size_t)(k0 + kk) * 64 + jj];
        }
        __syncthreads();
        #pragma unroll
        for (int kk = 0; kk < BK; kk++) {
            float a[4], bb[4];
            *(float4*)a  = *(const float4*)&As2[kk][ty * 4];
            *(float4*)bb = *(const float4*)&Bs2[kk][tx * 4];
            #pragma unroll
            for (int i = 0; i < 4; i++)
                #pragma unroll
                for (int jj = 0; jj < 4; jj++)
                    acc[i][jj] = fmaf(a[i], bb[jj], acc[i][jj]);
        }
        __syncthreads();
    }

    float bb0 = b[tx * 4 + 0], bb1 = b[tx * 4 + 1],
          bb2 = b[tx * 4 + 2], bb3 = b[tx * 4 + 3];
    #pragma unroll
    for (int i = 0; i < 4; i++) {
        int n = m0 + ty * 4 + i;
        float4 r;
        r.x = acc[i][0] + bb0;
        r.y = acc[i][1] + bb1;
        r.z = acc[i][2] + bb2;
        r.w = acc[i][3] + bb3;
        *(float4*)&g_P[(size_t)n * 64 + tx * 4] = r;
    }
}

// ============================================================
// Kernel 5: z_q[n] = P[tok[n]]
// ============================================================
__global__ __launch_bounds__(256) void gather_kernel(float* __restrict__ out)
{
    int idx = blockIdx.x * 256 + threadIdx.x;
    int n = idx >> 4;
    int c = idx & 15;
    int tok = g_tok[n];
    float4 v = *(const float4*)&g_P[(size_t)tok * 64 + c * 4];
    *(float4*)&out[(size_t)n * 64 + c * 4] = v;
}

// ============================================================
extern "C" void kernel_launch(void* const* d_in, const int* in_sizes, int n_in,
                              void* d_out, int out_size)
{
    const float* z      = (const float*)d_in[0];
    const float* emb_W  = (const float*)d_in[1];
    const float* pre_W  = (const float*)d_in[2];
    const float* pre_b  = (const float*)d_in[3];
    const float* post_W = (const float*)d_in[4];
    const float* post_b = (const float*)d_in[5];

    float* out = (float*)d_out;
    float* out_tok = out;
    float* out_zq  = out + N_TOK;

    cudaFuncSetAttribute(filter_kernel,
                         cudaFuncAttributeMaxDynamicSharedMemorySize, FIL_SMEM);

    e2_kernel    <<<V_SIZE, 128>>>(emb_W);
    pre_kernel   <<<N_TOK, 128>>>(z, pre_W, pre_b);
    pmat_kernel  <<<V_SIZE / BM, 256>>>(emb_W, post_W, post_b);

    dim3 fgrid(N_TOK / FM, NCH);
    filter_kernel<<<fgrid, 512, FIL_SMEM>>>();

    rescore_kernel<<<N_TOK / 8, 256>>>(emb_W, out_tok);
    gather_kernel<<<(N_TOK * 16) / 256, 256>>>(out_zq);
}

// round 9
// speedup vs baseline: 1.0351x; 1.0351x over previous
#include <cuda_runtime.h>
#include <cuda_bf16.h>
#include <mma.h>
#include <cstdint>

using namespace nvcuda;

#define N_TOK   65536
#define K_IN    64
#define E_DIM   512
#define V_SIZE  2048
#define CAND_CAP 16
#define NCH     2                 // codebook chunks (blockIdx.y)
#define VC      (V_SIZE / NCH)    // 1024 codes per CTA

typedef unsigned long long ull;

// ---- scratch (device globals: no runtime allocation allowed) ----
__device__ float           g_zp [(size_t)N_TOK * E_DIM];
__device__ __nv_bfloat16   g_zpH[(size_t)N_TOK * E_DIM];
__device__ __nv_bfloat16   g_ebH[(size_t)V_SIZE * E_DIM];
__device__ float           g_C  [N_TOK];
__device__ float           g_e2 [V_SIZE];
__device__ float           g_P  [(size_t)V_SIZE * 64];
__device__ int             g_cand[(size_t)N_TOK * (NCH * CAND_CAP)];
__device__ int             g_nc  [NCH][N_TOK];      // -1 = overflow

// ---- packed fp32x2 helpers ----
__device__ __forceinline__ ull fma2(ull a, ull b, ull c) {
    ull d; asm("fma.rn.f32x2 %0, %1, %2, %3;" : "=l"(d) : "l"(a), "l"(b), "l"(c)); return d;
}
__device__ __forceinline__ ull dup2(float x) {
    ull d; asm("mov.b64 %0, {%1, %1};" : "=l"(d) : "f"(x)); return d;
}
__device__ __forceinline__ ull pack2(float x, float y) {
    ull d; asm("mov.b64 %0, {%1, %2};" : "=l"(d) : "f"(x), "f"(y)); return d;
}
__device__ __forceinline__ float2 unpack2(ull v) {
    float2 r; asm("mov.b64 {%0, %1}, %2;" : "=f"(r.x), "=f"(r.y) : "l"(v)); return r;
}

// ============================================================
// Kernel 0: e2 + bf16 copy of emb
// ============================================================
__global__ void e2_kernel(const float* __restrict__ emb) {
    int v = blockIdx.x;
    const float* row = emb + (size_t)v * E_DIM;
    float s = 0.f;
    for (int k = threadIdx.x; k < E_DIM; k += 128) {
        float x = row[k];
        g_ebH[(size_t)v * E_DIM + k] = __float2bfloat16(x);
        s = fmaf(x, x, s);
    }
    for (int off = 16; off > 0; off >>= 1)
        s += __shfl_down_sync(0xffffffffu, s, off);
    __shared__ float ws[4];
    int lane = threadIdx.x & 31, warp = threadIdx.x >> 5;
    if (lane == 0) ws[warp] = s;
    __syncthreads();
    if (threadIdx.x == 0)
        g_e2[v] = ws[0] + ws[1] + ws[2] + ws[3];
}

// ============================================================
// Kernel 1: tiled pre GEMM.  zp = z @ pre_W + pre_b  (FFMA2)
// CTA: 64 rows x 128 cols; W tile staged ONCE in smem (32KB)
// instead of every row-block re-reading all of pre_W.
// Per-output chain: bias init, k=0..63 ascending  -> bitwise
// identical to the previously-validated pre_kernel.
// ============================================================
__global__ __launch_bounds__(256) void pre_gemm(
    const float* __restrict__ z, const float* __restrict__ W,
    const float* __restrict__ b)
{
    __shared__ float As[64][64];     // 16 KB : z tile (row-major)
    __shared__ float Ws[64][128];    // 32 KB : W tile

    int m0 = blockIdx.x * 64;
    int j0 = blockIdx.y * 128;
    int tid = threadIdx.x;
    int tx = tid & 15;     // col group (8 cols each)
    int ty = tid >> 4;     // row group (4 rows each)

    // load A tile: 64 rows x 64 k  (float4 chunks, 4/thread)
    #pragma unroll
    for (int l = 0; l < 4; l++) {
        int idx = tid + 256 * l;
        int row = idx >> 4, q = idx & 15;
        float4 v = *(const float4*)(z + (size_t)(m0 + row) * K_IN + q * 4);
        *(float4*)&As[row][q * 4] = v;
    }
    // load W tile: 64 k x 128 cols  (float4 chunks, 8/thread)
    #pragma unroll
    for (int l = 0; l < 8; l++) {
        int idx = tid + 256 * l;
        int row = idx >> 5, q = idx & 31;
        float4 v = *(const float4*)(W + (size_t)row * E_DIM + j0 + q * 4);
        *(float4*)&Ws[row][q * 4] = v;
    }
    __syncthreads();

    // accumulators: 4 rows x 8 cols as 4x4 f32x2 pairs; bias init
    float4 bl0 = *(const float4*)&b[j0 + tx * 8];
    float4 bl1 = *(const float4*)&b[j0 + tx * 8 + 4];
    ull acc[4][4];
    #pragma unroll
    for (int i = 0; i < 4; i++) {
        acc[i][0] = pack2(bl0.x, bl0.y);
        acc[i][1] = pack2(bl0.z, bl0.w);
        acc[i][2] = pack2(bl1.x, bl1.y);
        acc[i][3] = pack2(bl1.z, bl1.w);
    }

    #pragma unroll 8
    for (int kk = 0; kk < K_IN; kk++) {
        float a0 = As[ty * 4 + 0][kk];
        float a1 = As[ty * 4 + 1][kk];
        float a2 = As[ty * 4 + 2][kk];
        float a3 = As[ty * 4 + 3][kk];
        float4 w0 = *(const float4*)&Ws[kk][tx * 8];
        float4 w1 = *(const float4*)&Ws[kk][tx * 8 + 4];
        ull b0 = pack2(w0.x, w0.y), b1 = pack2(w0.z, w0.w);
        ull b2 = pack2(w1.x, w1.y), b3 = pack2(w1.z, w1.w);
        ull ad0 = dup2(a0), ad1 = dup2(a1), ad2 = dup2(a2), ad3 = dup2(a3);
        acc[0][0] = fma2(ad0, b0, acc[0][0]); acc[0][1] = fma2(ad0, b1, acc[0][1]);
        acc[0][2] = fma2(ad0, b2, acc[0][2]); acc[0][3] = fma2(ad0, b3, acc[0][3]);
        acc[1][0] = fma2(ad1, b0, acc[1][0]); acc[1][1] = fma2(ad1, b1, acc[1][1]);
        acc[1][2] = fma2(ad1, b2, acc[1][2]); acc[1][3] = fma2(ad1, b3, acc[1][3]);
        acc[2][0] = fma2(ad2, b0, acc[2][0]); acc[2][1] = fma2(ad2, b1, acc[2][1]);
        acc[2][2] = fma2(ad2, b2, acc[2][2]); acc[2][3] = fma2(ad2, b3, acc[2][3]);
        acc[3][0] = fma2(ad3, b0, acc[3][0]); acc[3][1] = fma2(ad3, b1, acc[3][1]);
        acc[3][2] = fma2(ad3, b2, acc[3][2]); acc[3][3] = fma2(ad3, b3, acc[3][3]);
    }

    #pragma unroll
    for (int i = 0; i < 4; i++) {
        int n = m0 + ty * 4 + i;
        float2 p0 = unpack2(acc[i][0]), p1 = unpack2(acc[i][1]);
        float2 p2 = unpack2(acc[i][2]), p3 = unpack2(acc[i][3]);
        float4 r0; r0.x = p0.x; r0.y = p0.y; r0.z = p1.x; r0.w = p1.y;
        float4 r1; r1.x = p2.x; r1.y = p2.y; r1.z = p3.x; r1.w = p3.y;
        float* dst = g_zp + (size_t)n * E_DIM + j0 + tx * 8;
        *(float4*)dst = r0;
        *(float4*)(dst + 4) = r1;
        __nv_bfloat16* hd = g_zpH + (size_t)n * E_DIM + j0 + tx * 8;
        *(__nv_bfloat162*)(hd + 0) = __floats2bfloat162_rn(r0.x, r0.y);
        *(__nv_bfloat162*)(hd + 2) = __floats2bfloat162_rn(r0.z, r0.w);
        *(__nv_bfloat162*)(hd + 4) = __floats2bfloat162_rn(r1.x, r1.y);
        *(__nv_bfloat162*)(hd + 6) = __floats2bfloat162_rn(r1.z, r1.w);
    }
}

// ============================================================
// Kernel 1b: C[n] = |zp[n]|^2  (one warp per row)
// Order differs from reference but is a constant per-row shift
// of all d[n,:] -> argmin invariant (validated empirically).
// ============================================================
__global__ __launch_bounds__(256) void c_kernel() {
    int n = blockIdx.x * 8 + (threadIdx.x >> 5);
    int lane = threadIdx.x & 31;
    const float* zr = g_zp + (size_t)n * E_DIM + lane * 16;
    float s = 0.f;
    #pragma unroll
    for (int q = 0; q < 4; q++) {
        float4 v = *(const float4*)(zr + q * 4);
        s = fmaf(v.x, v.x, s);
        s = fmaf(v.y, v.y, s);
        s = fmaf(v.z, v.z, s);
        s = fmaf(v.w, v.w, s);
    }
    #pragma unroll
    for (int off = 16; off > 0; off >>= 1)
        s += __shfl_xor_sync(0xffffffffu, s, off);
    if (lane == 0) g_C[n] = s;
}

// ============================================================
// Kernel 2: WMMA bf16 filter  (UNCHANGED from validated R7)
// ============================================================
#define FM 128
#define FN 128
#define A_LDM 520
#define B_LDM 40
#define D_LDM 132
#define N_VT (VC / FN)           // 8 vtiles per CTA
#define N_KC (E_DIM / 32)        // 16 k-chunks per vtile
#define N_CH (N_VT * N_KC)       // 128 chunks

#define OFF_A  0
#define OFF_B  (FM * A_LDM * 2)
#define OFF_D  (OFF_B + 2 * FN * B_LDM * 2)
#define OFF_E2 (OFF_D + FM * D_LDM * 4)
#define FIL_SMEM (OFF_E2 + FN * 4)

__global__ __launch_bounds__(512, 1) void filter_kernel()
{
    extern __shared__ unsigned char smem[];
    __nv_bfloat16* sA = (__nv_bfloat16*)(smem + OFF_A);
    __nv_bfloat16* sB = (__nv_bfloat16*)(smem + OFF_B);
    float*         sD = (float*)(smem + OFF_D);
    float*        sE2 = (float*)(smem + OFF_E2);

    int tid = threadIdx.x;
    int w   = tid >> 5;
    int wm  = w & 3;
    int wn  = w >> 2;
    int m0  = blockIdx.x * FM;
    int chunkId = blockIdx.y;
    int vc  = chunkId * VC;

    #pragma unroll
    for (int i = 0; i < 16; i++) {
        int idx = tid + 512 * i;
        int row = idx >> 6, c16 = idx & 63;
        uint4 v = *(const uint4*)(g_zpH + (size_t)(m0 + row) * E_DIM + c16 * 8);
        *(uint4*)((unsigned char*)sA + row * (A_LDM * 2) + c16 * 16) = v;
    }

    int bRow = tid >> 2, bQ = tid & 3;
    uint4 pB;
    #define LOADB(cc) do {                                                   \
        int _v  = (cc) >> 4, _kc = (cc) & 15;                                \
        pB = *(const uint4*)(g_ebH +                                         \
             (size_t)(vc + _v * FN + bRow) * E_DIM + _kc * 32 + bQ * 8);     \
    } while (0)
    #define STSB(bf) do {                                                    \
        *(uint4*)((unsigned char*)sB + (bf) * (FN * B_LDM * 2)               \
                  + bRow * (B_LDM * 2) + bQ * 16) = pB;                      \
    } while (0)

    float Ci = 0.f, thr = 0.f;
    if (tid < FM) {
        Ci  = g_C[m0 + tid];
        thr = sqrtf(Ci) * (0.01105f * 0.015625f) + 1e-4f;
    }
    float bd = 3.4e38f, bthr = 3.4e38f;
    float cdv[CAND_CAP];
    int   cvv[CAND_CAP];
    int   cnt = 0;
    bool  bad = false;

    wmma::fragment<wmma::accumulator, 16, 16, 16, float> cf[2][2];

    LOADB(0);
    STSB(0);
    LOADB(1);
    __syncthreads();

    #pragma unroll 1
    for (int c = 0; c < N_CH; c++) {
        int buf = c & 1;
        int kc  = c & 15;

        if (c + 1 < N_CH) {
            STSB(buf ^ 1);
            int nx = (c + 2 < N_CH) ? c + 2 : N_CH - 1;
            LOADB(nx);
        }

        if (kc == 0) {
            #pragma unroll
            for (int i = 0; i < 2; i++)
                #pragma unroll
                for (int j = 0; j < 2; j++)
                    wmma::fill_fragment(cf[i][j], 0.0f);
        }

        int ks0 = kc * 32;
        #pragma unroll
        for (int ks = 0; ks < 32; ks += 16) {
            wmma::fragment<wmma::matrix_a, 16, 16, 16, __nv_bfloat16, wmma::row_major> af[2];
            wmma::fragment<wmma::matrix_b, 16, 16, 16, __nv_bfloat16, wmma::col_major> bfr[2];
            #pragma unroll
            for (int i = 0; i < 2; i++)
                wmma::load_matrix_sync(af[i],
                    sA + (size_t)(wm * 32 + i * 16) * A_LDM + ks0 + ks, A_LDM);
            #pragma unroll
            for (int j = 0; j < 2; j++)
                wmma::load_matrix_sync(bfr[j],
                    sB + buf * (FN * B_LDM) + (size_t)(wn * 32 + j * 16) * B_LDM + ks, B_LDM);
            #pragma unroll
            for (int i = 0; i < 2; i++)
                #pragma unroll
                for (int j = 0; j < 2; j++)
                    wmma::mma_sync(cf[i][j], af[i], bfr[j], cf[i][j]);
        }

        __syncthreads();

        if (kc == 15) {
            int vt = c >> 4;
            #pragma unroll
            for (int i = 0; i < 2; i++)
                #pragma unroll
                for (int j = 0; j < 2; j++)
                    wmma::store_matrix_sync(
                        sD + (size_t)(wm * 32 + i * 16) * D_LDM + wn * 32 + j * 16,
                        cf[i][j], D_LDM, wmma::mem_row_major);
            if (tid < FN) sE2[tid] = g_e2[vc + vt * FN + tid];
            __syncthreads();

            if (tid < FM) {
                const float* drow = sD + (size_t)tid * D_LDM;
                #pragma unroll 1
                for (int cb = 0; cb < FN / 4; cb++) {
                    float4 d4 = *(const float4*)(drow + cb * 4);
                    float dv[4] = {d4.x, d4.y, d4.z, d4.w};
                    #pragma unroll
                    for (int q = 0; q < 4; q++) {
                        int vcode = vc + vt * FN + cb * 4 + q;
                        float d = fmaf(-2.0f, dv[q], Ci + sE2[cb * 4 + q]);
                        if (d < bd) { bd = d; bthr = bd + thr; }
                        if (d <= bthr) {
                            if (cnt == CAND_CAP) {
                                int jj = 0;
                                for (int i2 = 0; i2 < CAND_CAP; i2++)
                                    if (cdv[i2] <= bthr) { cdv[jj] = cdv[i2]; cvv[jj] = cvv[i2]; jj++; }
                                cnt = jj;
                            }
                            if (cnt == CAND_CAP) bad = true;
                            else { cdv[cnt] = d; cvv[cnt] = vcode; cnt++; }
                        }
                    }
                }
            }
            __syncthreads();
        }
    }

    if (tid < FM) {
        int n = m0 + tid;
        int jj = 0;
        for (int i2 = 0; i2 < cnt; i2++)
            if (cdv[i2] <= bthr) { cvv[jj] = cvv[i2]; jj++; }
        g_nc[chunkId][n] = bad ? -1 : jj;
        int* dst = g_cand + (size_t)n * (NCH * CAND_CAP) + chunkId * CAND_CAP;
        for (int i2 = 0; i2 < jj; i2++) dst[i2] = cvv[i2];
    }
    #undef LOADB
    #undef STSB
}

// ============================================================
// Kernel 3: exact rescore + fused output (tokens AND z_q).
// Sequential-k fp32 chain (bitwise-proven); first-index ties.
// ============================================================
__global__ __launch_bounds__(256) void rescore_kernel(
    const float* __restrict__ emb, float* __restrict__ out_tok,
    float* __restrict__ out_zq)
{
    int n    = blockIdx.x * 8 + (threadIdx.x >> 5);
    int lane = threadIdx.x & 31;
    int nc0  = g_nc[0][n];
    int nc1  = g_nc[1][n];

    const float* zr = g_zp + (size_t)n * E_DIM;
    float bdv = 3.4e38f;
    int   bvi = 0x7fffffff;

    if (nc0 >= 0 && nc1 >= 0) {
        int v = -1;
        if (lane < 16) { if (lane < nc0) v = g_cand[(size_t)n * 32 + lane]; }
        else           { if (lane - 16 < nc1) v = g_cand[(size_t)n * 32 + 16 + (lane - 16)]; }
        if (v >= 0) {
            const float* er = emb + (size_t)v * E_DIM;
            float dot = 0.f;
            #pragma unroll 8
            for (int k = 0; k < E_DIM; k += 4) {
                float4 a = *(const float4*)(zr + k);
                float4 bb = *(const float4*)(er + k);
                dot = fmaf(a.x, bb.x, dot);
                dot = fmaf(a.y, bb.y, dot);
                dot = fmaf(a.z, bb.z, dot);
                dot = fmaf(a.w, bb.w, dot);
            }
            bdv = fmaf(-2.0f, dot, g_C[n] + g_e2[v]);
            bvi = v;
        }
    } else {
        for (int v = lane; v < V_SIZE; v += 32) {
            const float* er = emb + (size_t)v * E_DIM;
            float dot = 0.f;
            #pragma unroll 8
            for (int k = 0; k < E_DIM; k += 4) {
                float4 a = *(const float4*)(zr + k);
                float4 bb = *(const float4*)(er + k);
                dot = fmaf(a.x, bb.x, dot);
                dot = fmaf(a.y, bb.y, dot);
                dot = fmaf(a.z, bb.z, dot);
                dot = fmaf(a.w, bb.w, dot);
            }
            float d = fmaf(-2.0f, dot, g_C[n] + g_e2[v]);
            if (d < bdv || (d == bdv && v < bvi)) { bdv = d; bvi = v; }
        }
    }

    #pragma unroll
    for (int off = 16; off > 0; off >>= 1) {
        float od = __shfl_xor_sync(0xffffffffu, bdv, off);
        int   ov = __shfl_xor_sync(0xffffffffu, bvi, off);
        if (od < bdv || (od == bdv && ov < bvi)) { bdv = od; bvi = ov; }
    }
    // all lanes now hold the winning index
    if (lane == 0) out_tok[n] = (float)bvi;
    if (lane < 16) {
        float4 v = *(const float4*)&g_P[(size_t)bvi * 64 + lane * 4];
        *(float4*)&out_zq[(size_t)n * 64 + lane * 4] = v;
    }
}

// ============================================================
// Kernel 4: P = emb @ post_W + post_b   [2048, 64]
// ============================================================
#define BM 64
#define BK 32

__global__ __launch_bounds__(256) void pmat_kernel(
    const float* __restrict__ emb, const float* __restrict__ W,
    const float* __restrict__ b)
{
    __shared__ float As2[BK][BM + 4];
    __shared__ float Bs2[BK][64 + 4];

    int m0  = blockIdx.x * BM;
    int tid = threadIdx.x;
    int tx  = tid & 15;
    int ty  = tid >> 4;

    float acc[4][4];
    #pragma unroll
    for (int i = 0; i < 4; i++)
        #pragma unroll
        for (int jj = 0; jj < 4; jj++) acc[i][jj] = 0.f;

    for (int k0 = 0; k0 < E_DIM; k0 += BK) {
        #pragma unroll
        for (int i = 0; i < 8; i++) {
            int idx = tid + 256 * i;
            int m = idx >> 5, kk = idx & 31;
            As2[kk][m] = emb[(size_t)(m0 + m) * E_DIM + k0 + kk];
        }
        #pragma unroll
        for (int i = 0; i < 8; i++) {
            int idx = tid + 256 * i;
            int kk = idx >> 6, jj = idx & 63;
            Bs2[kk][jj] = W[(size_t)(k0 + kk) * 64 + jj];
        }
        __syncthreads();
        #pragma unroll
        for (int kk = 0; kk < BK; kk++) {
            float a[4], bb[4];
            *(float4*)a  = *(const float4*)&As2[kk][ty * 4];
            *(float4*)bb = *(const float4*)&Bs2[kk][tx * 4];
            #pragma unroll
            for (int i = 0; i < 4; i++)
                #pragma unroll
                for (int jj = 0; jj < 4; jj++)
                    acc[i][jj] = fmaf(a[i], bb[jj], acc[i][jj]);
        }
        __syncthreads();
    }

    float bb0 = b[tx * 4 + 0], bb1 = b[tx * 4 + 1],
          bb2 = b[tx * 4 + 2], bb3 = b[tx * 4 + 3];
    #pragma unroll
    for (int i = 0; i < 4; i++) {
        int n = m0 + ty * 4 + i;
        float4 r;
        r.x = acc[i][0] + bb0;
        r.y = acc[i][1] + bb1;
        r.z = acc[i][2] + bb2;
        r.w = acc[i][3] + bb3;
        *(float4*)&g_P[(size_t)n * 64 + tx * 4] = r;
    }
}

// ============================================================
extern "C" void kernel_launch(void* const* d_in, const int* in_sizes, int n_in,
                              void* d_out, int out_size)
{
    const float* z      = (const float*)d_in[0];
    const float* emb_W  = (const float*)d_in[1];
    const float* pre_W  = (const float*)d_in[2];
    const float* pre_b  = (const float*)d_in[3];
    const float* post_W = (const float*)d_in[4];
    const float* post_b = (const float*)d_in[5];

    float* out = (float*)d_out;
    float* out_tok = out;
    float* out_zq  = out + N_TOK;

    cudaFuncSetAttribute(filter_kernel,
                         cudaFuncAttributeMaxDynamicSharedMemorySize, FIL_SMEM);

    e2_kernel <<<V_SIZE, 128>>>(emb_W);

    dim3 pgrid(N_TOK / 64, E_DIM / 128);
    pre_gemm  <<<pgrid, 256>>>(z, pre_W, pre_b);
    c_kernel  <<<N_TOK / 8, 256>>>();

    pmat_kernel<<<V_SIZE / BM, 256>>>(emb_W, post_W, post_b);

    dim3 fgrid(N_TOK / FM, NCH);
    filter_kernel<<<fgrid, 512, FIL_SMEM>>>();

    rescore_kernel<<<N_TOK / 8, 256>>>(emb_W, out_tok, out_zq);
}

// round 10
// speedup vs baseline: 1.2711x; 1.2280x over previous
#include <cuda_runtime.h>
#include <cstdint>

#define N_TOK   65536
#define K_IN    64
#define E_DIM   512
#define V_SIZE  2048
#define NCHUNK  2
#define VCHUNK  (V_SIZE / NCHUNK)

typedef unsigned long long ull;

// ---- scratch ----
__device__ float g_zp[(size_t)N_TOK * E_DIM];
__device__ float g_C [N_TOK];
__device__ float g_e2[V_SIZE];
__device__ float g_P [(size_t)V_SIZE * 64];
__device__ float g_pv[NCHUNK][N_TOK];
__device__ int   g_pi[NCHUNK][N_TOK];

// ---- packed fp32x2 helpers (exact IEEE fp32 per lane) ----
__device__ __forceinline__ ull fma2(ull a, ull b, ull c) {
    ull d; asm("fma.rn.f32x2 %0, %1, %2, %3;" : "=l"(d) : "l"(a), "l"(b), "l"(c)); return d;
}
__device__ __forceinline__ ull dup2(float x) {
    ull d; asm("mov.b64 %0, {%1, %1};" : "=l"(d) : "f"(x)); return d;
}
__device__ __forceinline__ ull pack2(float x, float y) {
    ull d; asm("mov.b64 %0, {%1, %2};" : "=l"(d) : "f"(x), "f"(y)); return d;
}
__device__ __forceinline__ float2 unpack2(ull v) {
    float2 r; asm("mov.b64 {%0, %1}, %2;" : "=f"(r.x), "=f"(r.y) : "l"(v)); return r;
}

// ============================================================
// Kernel 0: e2[v] = sum_k emb[v,k]^2   (validated)
// ============================================================
__global__ void e2_kernel(const float* __restrict__ emb) {
    int v = blockIdx.x;
    const float* row = emb + (size_t)v * E_DIM;
    float s = 0.f;
    for (int k = threadIdx.x; k < E_DIM; k += 128) {
        float x = row[k];
        s = fmaf(x, x, s);
    }
    for (int off = 16; off > 0; off >>= 1)
        s += __shfl_down_sync(0xffffffffu, s, off);
    __shared__ float ws[4];
    int lane = threadIdx.x & 31, warp = threadIdx.x >> 5;
    if (lane == 0) ws[warp] = s;
    __syncthreads();
    if (threadIdx.x == 0)
        g_e2[v] = ws[0] + ws[1] + ws[2] + ws[3];
}

// ============================================================
// Kernel 1: tiled pre GEMM (validated R8, bf16 stores removed)
// ============================================================
__global__ __launch_bounds__(256) void pre_gemm(
    const float* __restrict__ z, const float* __restrict__ W,
    const float* __restrict__ b)
{
    __shared__ float As[64][64];
    __shared__ float Ws[64][128];

    int m0 = blockIdx.x * 64;
    int j0 = blockIdx.y * 128;
    int tid = threadIdx.x;
    int tx = tid & 15;
    int ty = tid >> 4;

    #pragma unroll
    for (int l = 0; l < 4; l++) {
        int idx = tid + 256 * l;
        int row = idx >> 4, q = idx & 15;
        float4 v = *(const float4*)(z + (size_t)(m0 + row) * K_IN + q * 4);
        *(float4*)&As[row][q * 4] = v;
    }
    #pragma unroll
    for (int l = 0; l < 8; l++) {
        int idx = tid + 256 * l;
        int row = idx >> 5, q = idx & 31;
        float4 v = *(const float4*)(W + (size_t)row * E_DIM + j0 + q * 4);
        *(float4*)&Ws[row][q * 4] = v;
    }
    __syncthreads();

    float4 bl0 = *(const float4*)&b[j0 + tx * 8];
    float4 bl1 = *(const float4*)&b[j0 + tx * 8 + 4];
    ull acc[4][4];
    #pragma unroll
    for (int i = 0; i < 4; i++) {
        acc[i][0] = pack2(bl0.x, bl0.y);
        acc[i][1] = pack2(bl0.z, bl0.w);
        acc[i][2] = pack2(bl1.x, bl1.y);
        acc[i][3] = pack2(bl1.z, bl1.w);
    }

    #pragma unroll 8
    for (int kk = 0; kk < K_IN; kk++) {
        float a0 = As[ty * 4 + 0][kk];
        float a1 = As[ty * 4 + 1][kk];
        float a2 = As[ty * 4 + 2][kk];
        float a3 = As[ty * 4 + 3][kk];
        float4 w0 = *(const float4*)&Ws[kk][tx * 8];
        float4 w1 = *(const float4*)&Ws[kk][tx * 8 + 4];
        ull b0 = pack2(w0.x, w0.y), b1 = pack2(w0.z, w0.w);
        ull b2 = pack2(w1.x, w1.y), b3 = pack2(w1.z, w1.w);
        ull ad0 = dup2(a0), ad1 = dup2(a1), ad2 = dup2(a2), ad3 = dup2(a3);
        acc[0][0] = fma2(ad0, b0, acc[0][0]); acc[0][1] = fma2(ad0, b1, acc[0][1]);
        acc[0][2] = fma2(ad0, b2, acc[0][2]); acc[0][3] = fma2(ad0, b3, acc[0][3]);
        acc[1][0] = fma2(ad1, b0, acc[1][0]); acc[1][1] = fma2(ad1, b1, acc[1][1]);
        acc[1][2] = fma2(ad1, b2, acc[1][2]); acc[1][3] = fma2(ad1, b3, acc[1][3]);
        acc[2][0] = fma2(ad2, b0, acc[2][0]); acc[2][1] = fma2(ad2, b1, acc[2][1]);
        acc[2][2] = fma2(ad2, b2, acc[2][2]); acc[2][3] = fma2(ad2, b3, acc[2][3]);
        acc[3][0] = fma2(ad3, b0, acc[3][0]); acc[3][1] = fma2(ad3, b1, acc[3][1]);
        acc[3][2] = fma2(ad3, b2, acc[3][2]); acc[3][3] = fma2(ad3, b3, acc[3][3]);
    }

    #pragma unroll
    for (int i = 0; i < 4; i++) {
        int n = m0 + ty * 4 + i;
        float2 p0 = unpack2(acc[i][0]), p1 = unpack2(acc[i][1]);
        float2 p2 = unpack2(acc[i][2]), p3 = unpack2(acc[i][3]);
        float4 r0; r0.x = p0.x; r0.y = p0.y; r0.z = p1.x; r0.w = p1.y;
        float4 r1; r1.x = p2.x; r1.y = p2.y; r1.z = p3.x; r1.w = p3.y;
        float* dst = g_zp + (size_t)n * E_DIM + j0 + tx * 8;
        *(float4*)dst = r0;
        *(float4*)(dst + 4) = r1;
    }
}

// ============================================================
// Kernel 1b: C[n] = |zp[n]|^2  (validated R8; order argmin-safe)
// ============================================================
__global__ __launch_bounds__(256) void c_kernel() {
    int n = blockIdx.x * 8 + (threadIdx.x >> 5);
    int lane = threadIdx.x & 31;
    const float* zr = g_zp + (size_t)n * E_DIM + lane * 16;
    float s = 0.f;
    #pragma unroll
    for (int q = 0; q < 4; q++) {
        float4 v = *(const float4*)(zr + q * 4);
        s = fmaf(v.x, v.x, s);
        s = fmaf(v.y, v.y, s);
        s = fmaf(v.z, v.z, s);
        s = fmaf(v.w, v.w, s);
    }
    #pragma unroll
    for (int off = 16; off > 0; off >>= 1)
        s += __shfl_xor_sync(0xffffffffu, s, off);
    if (lane == 0) g_C[n] = s;
}

// ============================================================
// Kernel 2: fused distance GEMM + argmin (R4 backbone; the
// only change: STS+LDG for next tile moved between kk=7 and
// kk=8 so LSU work overlaps FFMA2. Same buffers, same barrier
// -> identical FMA chains -> bitwise tokens.
// ============================================================
#define DBM 128
#define DBV 256
#define DBK 16
#define NKT (E_DIM / DBK)          // 32
#define NVT (VCHUNK / DBV)         // 4
#define NT  (NKT * NVT)            // 128

__global__ __launch_bounds__(256, 1) void dist_kernel(
    const float* __restrict__ emb)
{
    __shared__ float As[2][DBK][DBM];
    __shared__ float Bs[2][DBK][DBV];

    int m0 = blockIdx.x * DBM;
    int chunk = blockIdx.y;
    int vc = chunk * VCHUNK;

    int tid = threadIdx.x;
    int tx  = tid & 15;
    int ty  = tid >> 4;
    int row0 = ty * 8;

    int mA  = tid >> 2;
    int kq4 = (tid & 3) * 4;
    int sw  = kq4 << 1;
    int mAx = mA ^ sw;

    const float* aBase = g_zp + (size_t)(m0 + mA) * E_DIM + kq4;
    const float* bBase = emb  + (size_t)(vc + mA) * E_DIM + kq4;

    float Ci[8];
    #pragma unroll
    for (int i = 0; i < 8; i++) Ci[i] = g_C[m0 + row0 + i];

    float bestv[8];
    int   besti[8];
    #pragma unroll
    for (int i = 0; i < 8; i++) { bestv[i] = 3.4e38f; besti[i] = 0; }

    ull acc[8][8];
    float4 pA0, pA1, pB0, pB1, pB2, pB3;

    #define LOAD_TILE(tt) do {                                              \
        int _k = ((tt) & (NKT - 1)) * DBK;                                  \
        int _v = ((tt) >> 5) * DBV;                                         \
        pA0 = *(const float4*)(aBase + _k);                                 \
        pA1 = *(const float4*)(aBase + (size_t)64 * E_DIM + _k);            \
        const float* _bb = bBase + (size_t)_v * E_DIM + _k;                 \
        pB0 = *(const float4*)(_bb);                                        \
        pB1 = *(const float4*)(_bb + (size_t)64  * E_DIM);                  \
        pB2 = *(const float4*)(_bb + (size_t)128 * E_DIM);                  \
        pB3 = *(const float4*)(_bb + (size_t)192 * E_DIM);                  \
    } while (0)

    #define STS_TILE(bf) do {                                               \
        float* _a = &As[bf][kq4][0];                                        \
        _a[0*DBM + mAx]      = pA0.x; _a[1*DBM + mAx]      = pA0.y;         \
        _a[2*DBM + mAx]      = pA0.z; _a[3*DBM + mAx]      = pA0.w;         \
        _a[0*DBM + mAx + 64] = pA1.x; _a[1*DBM + mAx + 64] = pA1.y;         \
        _a[2*DBM + mAx + 64] = pA1.z; _a[3*DBM + mAx + 64] = pA1.w;         \
        float* _b = &Bs[bf][kq4][0];                                        \
        _b[0*DBV + mAx]       = pB0.x; _b[1*DBV + mAx]       = pB0.y;       \
        _b[2*DBV + mAx]       = pB0.z; _b[3*DBV + mAx]       = pB0.w;       \
        _b[0*DBV + mAx + 64]  = pB1.x; _b[1*DBV + mAx + 64]  = pB1.y;       \
        _b[2*DBV + mAx + 64]  = pB1.z; _b[3*DBV + mAx + 64]  = pB1.w;       \
        _b[0*DBV + mAx + 128] = pB2.x; _b[1*DBV + mAx + 128] = pB2.y;       \
        _b[2*DBV + mAx + 128] = pB2.z; _b[3*DBV + mAx + 128] = pB2.w;       \
        _b[0*DBV + mAx + 192] = pB3.x; _b[1*DBV + mAx + 192] = pB3.y;       \
        _b[2*DBV + mAx + 192] = pB3.z; _b[3*DBV + mAx + 192] = pB3.w;       \
    } while (0)

    #define COMPUTE_KK(bf, kk) do {                                         \
        const int s = ((kk) & 12) << 1;                                     \
        float4 a01 = *(const float4*)&As[bf][kk][(row0 ^ s)];               \
        float4 a23 = *(const float4*)&As[bf][kk][(row0 ^ s) + 4];           \
        ull ad[8];                                                          \
        ad[0] = dup2(a01.x); ad[1] = dup2(a01.y);                           \
        ad[2] = dup2(a01.z); ad[3] = dup2(a01.w);                           \
        ad[4] = dup2(a23.x); ad[5] = dup2(a23.y);                           \
        ad[6] = dup2(a23.z); ad[7] = dup2(a23.w);                           \
        _Pragma("unroll")                                                   \
        for (int g = 0; g < 4; g++) {                                       \
            float4 b = *(const float4*)&Bs[bf][kk][(((g * 16 + tx) * 4) ^ s)]; \
            ull b0 = pack2(b.x, b.y);                                       \
            ull b1 = pack2(b.z, b.w);                                       \
            _Pragma("unroll")                                               \
            for (int i = 0; i < 8; i++) {                                   \
                acc[i][g * 2 + 0] = fma2(ad[i], b0, acc[i][g * 2 + 0]);     \
                acc[i][g * 2 + 1] = fma2(ad[i], b1, acc[i][g * 2 + 1]);     \
            }                                                               \
        }                                                                   \
    } while (0)

    LOAD_TILE(0);
    STS_TILE(0);
    LOAD_TILE(1);
    __syncthreads();

    for (int t = 0; t < NT; t++) {
        int buf = t & 1;

        if ((t & (NKT - 1)) == 0) {
            #pragma unroll
            for (int i = 0; i < 8; i++)
                #pragma unroll
                for (int j = 0; j < 8; j++) acc[i][j] = 0ull;
        }

        // first half of compute
        #pragma unroll
        for (int kk = 0; kk < DBK / 2; kk++) COMPUTE_KK(buf, kk);

        // overlap LSU work with FFMA2: store t+1 into other buffer,
        // prefetch t+2 into regs
        if (t + 1 < NT) {
            STS_TILE(buf ^ 1);
            int tt = (t + 2 < NT) ? t + 2 : NT - 1;
            LOAD_TILE(tt);
        }

        // second half of compute
        #pragma unroll
        for (int kk = DBK / 2; kk < DBK; kk++) COMPUTE_KK(buf, kk);

        __syncthreads();

        if ((t & (NKT - 1)) == NKT - 1) {
            int v0 = vc + (t >> 5) * DBV;
            #pragma unroll
            for (int g = 0; g < 4; g++) {
                int vb = v0 + (g * 16 + tx) * 4;
                float e0 = g_e2[vb + 0];
                float e1 = g_e2[vb + 1];
                float e2v = g_e2[vb + 2];
                float e3 = g_e2[vb + 3];
                #pragma unroll
                for (int i = 0; i < 8; i++) {
                    float2 p0 = unpack2(acc[i][g * 2 + 0]);
                    float2 p1 = unpack2(acc[i][g * 2 + 1]);
                    float d;
                    d = fmaf(-2.0f, p0.x, Ci[i] + e0);
                    if (d < bestv[i]) { bestv[i] = d; besti[i] = vb + 0; }
                    d = fmaf(-2.0f, p0.y, Ci[i] + e1);
                    if (d < bestv[i]) { bestv[i] = d; besti[i] = vb + 1; }
                    d = fmaf(-2.0f, p1.x, Ci[i] + e2v);
                    if (d < bestv[i]) { bestv[i] = d; besti[i] = vb + 2; }
                    d = fmaf(-2.0f, p1.y, Ci[i] + e3);
                    if (d < bestv[i]) { bestv[i] = d; besti[i] = vb + 3; }
                }
            }
        }
    }

    #pragma unroll
    for (int i = 0; i < 8; i++) {
        float v = bestv[i];
        int   idx = besti[i];
        #pragma unroll
        for (int off = 8; off > 0; off >>= 1) {
            float ov = __shfl_xor_sync(0xffffffffu, v, off);
            int   oi = __shfl_xor_sync(0xffffffffu, idx, off);
            if (ov < v || (ov == v && oi < idx)) { v = ov; idx = oi; }
        }
        if (tx == 0) {
            int n = m0 + row0 + i;
            g_pv[chunk][n] = v;
            g_pi[chunk][n] = idx;
        }
    }
    #undef LOAD_TILE
    #undef STS_TILE
    #undef COMPUTE_KK
}

// ============================================================
// Kernel 3: P = emb @ post_W + post_b  (validated)
// ============================================================
#define BM 64
#define BK 32

__global__ __launch_bounds__(256) void pmat_kernel(
    const float* __restrict__ emb, const float* __restrict__ W,
    const float* __restrict__ b)
{
    __shared__ float As2[BK][BM + 4];
    __shared__ float Bs2[BK][64 + 4];

    int m0  = blockIdx.x * BM;
    int tid = threadIdx.x;
    int tx  = tid & 15;
    int ty  = tid >> 4;

    float acc[4][4];
    #pragma unroll
    for (int i = 0; i < 4; i++)
        #pragma unroll
        for (int jj = 0; jj < 4; jj++) acc[i][jj] = 0.f;

    for (int k0 = 0; k0 < E_DIM; k0 += BK) {
        #pragma unroll
        for (int i = 0; i < 8; i++) {
            int idx = tid + 256 * i;
            int m = idx >> 5, kk = idx & 31;
            As2[kk][m] = emb[(size_t)(m0 + m) * E_DIM + k0 + kk];
        }
        #pragma unroll
        for (int i = 0; i < 8; i++) {
            int idx = tid + 256 * i;
            int kk = idx >> 6, jj = idx & 63;
            Bs2[kk][jj] = W[(size_t)(k0 + kk) * 64 + jj];
        }
        __syncthreads();
        #pragma unroll
        for (int kk = 0; kk < BK; kk++) {
            float a[4], bb[4];
            *(float4*)a  = *(const float4*)&As2[kk][ty * 4];
            *(float4*)bb = *(const float4*)&Bs2[kk][tx * 4];
            #pragma unroll
            for (int i = 0; i < 4; i++)
                #pragma unroll
                for (int jj = 0; jj < 4; jj++)
                    acc[i][jj] = fmaf(a[i], bb[jj], acc[i][jj]);
        }
        __syncthreads();
    }

    float bb0 = b[tx * 4 + 0], bb1 = b[tx * 4 + 1],
          bb2 = b[tx * 4 + 2], bb3 = b[tx * 4 + 3];
    #pragma unroll
    for (int i = 0; i < 4; i++) {
        int n = m0 + ty * 4 + i;
        float4 r;
        r.x = acc[i][0] + bb0;
        r.y = acc[i][1] + bb1;
        r.z = acc[i][2] + bb2;
        r.w = acc[i][3] + bb3;
        *(float4*)&g_P[(size_t)n * 64 + tx * 4] = r;
    }
}

// ============================================================
// Kernel 4: merge per-chunk argmins + write tokens AND z_q rows
// (one warp per row; strict < over ascending chunks = first-min)
// ============================================================
__global__ __launch_bounds__(256) void merge_gather(
    float* __restrict__ out_tok, float* __restrict__ out_zq)
{
    int n    = blockIdx.x * 8 + (threadIdx.x >> 5);
    int lane = threadIdx.x & 31;

    int tok = 0;
    if (lane == 0) {
        float bv = g_pv[0][n];
        int   bi = g_pi[0][n];
        #pragma unroll
        for (int c = 1; c < NCHUNK; c++) {
            float v = g_pv[c][n];
            int   i = g_pi[c][n];
            if (v < bv) { bv = v; bi = i; }
        }
        tok = bi;
        out_tok[n] = (float)bi;
    }
    tok = __shfl_sync(0xffffffffu, tok, 0);
    if (lane < 16) {
        float4 v = *(const float4*)&g_P[(size_t)tok * 64 + lane * 4];
        *(float4*)&out_zq[(size_t)n * 64 + lane * 4] = v;
    }
}

// ============================================================
extern "C" void kernel_launch(void* const* d_in, const int* in_sizes, int n_in,
                              void* d_out, int out_size)
{
    const float* z      = (const float*)d_in[0];
    const float* emb_W  = (const float*)d_in[1];
    const float* pre_W  = (const float*)d_in[2];
    const float* pre_b  = (const float*)d_in[3];
    const float* post_W = (const float*)d_in[4];
    const float* post_b = (const float*)d_in[5];

    float* out = (float*)d_out;
    float* out_tok = out;
    float* out_zq  = out + N_TOK;

    e2_kernel <<<V_SIZE, 128>>>(emb_W);

    dim3 pgrid(N_TOK / 64, E_DIM / 128);
    pre_gemm  <<<pgrid, 256>>>(z, pre_W, pre_b);
    c_kernel  <<<N_TOK / 8, 256>>>();

    pmat_kernel<<<V_SIZE / BM, 256>>>(emb_W, post_W, post_b);

    dim3 dgrid(N_TOK / DBM, NCHUNK);
    dist_kernel<<<dgrid, 256>>>(emb_W);

    merge_gather<<<N_TOK / 8, 256>>>(out_tok, out_zq);
}

// round 11
// speedup vs baseline: 1.2741x; 1.0024x over previous
#include <cuda_runtime.h>
#include <cstdint>

#define N_TOK   65536
#define K_IN    64
#define E_DIM   512
#define V_SIZE  2048
#define NCHUNK  2
#define VCHUNK  (V_SIZE / NCHUNK)
#define PKB     8                    // pmat split-K factor

typedef unsigned long long ull;

// ---- scratch ----
__device__ float g_zp[(size_t)N_TOK * E_DIM];
__device__ float g_Cp[4][N_TOK];                 // per-j-block |zp|^2 partials
__device__ float g_e2[V_SIZE];
__device__ float g_Pp[PKB][(size_t)V_SIZE * 64]; // pmat k-partials
__device__ float g_pv[NCHUNK][N_TOK];
__device__ int   g_pi[NCHUNK][N_TOK];

// ---- packed fp32x2 helpers (exact IEEE fp32 per lane) ----
__device__ __forceinline__ ull fma2(ull a, ull b, ull c) {
    ull d; asm("fma.rn.f32x2 %0, %1, %2, %3;" : "=l"(d) : "l"(a), "l"(b), "l"(c)); return d;
}
__device__ __forceinline__ ull dup2(float x) {
    ull d; asm("mov.b64 %0, {%1, %1};" : "=l"(d) : "f"(x)); return d;
}
__device__ __forceinline__ ull pack2(float x, float y) {
    ull d; asm("mov.b64 %0, {%1, %2};" : "=l"(d) : "f"(x), "f"(y)); return d;
}
__device__ __forceinline__ float2 unpack2(ull v) {
    float2 r; asm("mov.b64 {%0, %1}, %2;" : "=f"(r.x), "=f"(r.y) : "l"(v)); return r;
}

// ============================================================
// Kernel 0: e2[v] = sum_k emb[v,k]^2   (validated; bitwise path)
// ============================================================
__global__ void e2_kernel(const float* __restrict__ emb) {
    int v = blockIdx.x;
    const float* row = emb + (size_t)v * E_DIM;
    float s = 0.f;
    for (int k = threadIdx.x; k < E_DIM; k += 128) {
        float x = row[k];
        s = fmaf(x, x, s);
    }
    for (int off = 16; off > 0; off >>= 1)
        s += __shfl_down_sync(0xffffffffu, s, off);
    __shared__ float ws[4];
    int lane = threadIdx.x & 31, warp = threadIdx.x >> 5;
    if (lane == 0) ws[warp] = s;
    __syncthreads();
    if (threadIdx.x == 0)
        g_e2[v] = ws[0] + ws[1] + ws[2] + ws[3];
}

// ============================================================
// Kernel 1: tiled pre GEMM (validated) + fused C partials.
// zp chain unchanged (bias init, k ascending) -> bitwise zp.
// C partial: fixed-order per-thread chain + 16-lane shfl tree,
// deterministic; dist sums the 4 j-block partials ascending.
// ============================================================
__global__ __launch_bounds__(256) void pre_gemm(
    const float* __restrict__ z, const float* __restrict__ W,
    const float* __restrict__ b)
{
    __shared__ float As[64][64];
    __shared__ float Ws[64][128];

    int m0 = blockIdx.x * 64;
    int jb = blockIdx.y;
    int j0 = jb * 128;
    int tid = threadIdx.x;
    int tx = tid & 15;
    int ty = tid >> 4;

    #pragma unroll
    for (int l = 0; l < 4; l++) {
        int idx = tid + 256 * l;
        int row = idx >> 4, q = idx & 15;
        float4 v = *(const float4*)(z + (size_t)(m0 + row) * K_IN + q * 4);
        *(float4*)&As[row][q * 4] = v;
    }
    #pragma unroll
    for (int l = 0; l < 8; l++) {
        int idx = tid + 256 * l;
        int row = idx >> 5, q = idx & 31;
        float4 v = *(const float4*)(W + (size_t)row * E_DIM + j0 + q * 4);
        *(float4*)&Ws[row][q * 4] = v;
    }
    __syncthreads();

    float4 bl0 = *(const float4*)&b[j0 + tx * 8];
    float4 bl1 = *(const float4*)&b[j0 + tx * 8 + 4];
    ull acc[4][4];
    #pragma unroll
    for (int i = 0; i < 4; i++) {
        acc[i][0] = pack2(bl0.x, bl0.y);
        acc[i][1] = pack2(bl0.z, bl0.w);
        acc[i][2] = pack2(bl1.x, bl1.y);
        acc[i][3] = pack2(bl1.z, bl1.w);
    }

    #pragma unroll 8
    for (int kk = 0; kk < K_IN; kk++) {
        float a0 = As[ty * 4 + 0][kk];
        float a1 = As[ty * 4 + 1][kk];
        float a2 = As[ty * 4 + 2][kk];
        float a3 = As[ty * 4 + 3][kk];
        float4 w0 = *(const float4*)&Ws[kk][tx * 8];
        float4 w1 = *(const float4*)&Ws[kk][tx * 8 + 4];
        ull b0 = pack2(w0.x, w0.y), b1 = pack2(w0.z, w0.w);
        ull b2 = pack2(w1.x, w1.y), b3 = pack2(w1.z, w1.w);
        ull ad0 = dup2(a0), ad1 = dup2(a1), ad2 = dup2(a2), ad3 = dup2(a3);
        acc[0][0] = fma2(ad0, b0, acc[0][0]); acc[0][1] = fma2(ad0, b1, acc[0][1]);
        acc[0][2] = fma2(ad0, b2, acc[0][2]); acc[0][3] = fma2(ad0, b3, acc[0][3]);
        acc[1][0] = fma2(ad1, b0, acc[1][0]); acc[1][1] = fma2(ad1, b1, acc[1][1]);
        acc[1][2] = fma2(ad1, b2, acc[1][2]); acc[1][3] = fma2(ad1, b3, acc[1][3]);
        acc[2][0] = fma2(ad2, b0, acc[2][0]); acc[2][1] = fma2(ad2, b1, acc[2][1]);
        acc[2][2] = fma2(ad2, b2, acc[2][2]); acc[2][3] = fma2(ad2, b3, acc[2][3]);
        acc[3][0] = fma2(ad3, b0, acc[3][0]); acc[3][1] = fma2(ad3, b1, acc[3][1]);
        acc[3][2] = fma2(ad3, b2, acc[3][2]); acc[3][3] = fma2(ad3, b3, acc[3][3]);
    }

    #pragma unroll
    for (int i = 0; i < 4; i++) {
        int n = m0 + ty * 4 + i;
        float2 p0 = unpack2(acc[i][0]), p1 = unpack2(acc[i][1]);
        float2 p2 = unpack2(acc[i][2]), p3 = unpack2(acc[i][3]);
        float4 r0; r0.x = p0.x; r0.y = p0.y; r0.z = p1.x; r0.w = p1.y;
        float4 r1; r1.x = p2.x; r1.y = p2.y; r1.z = p3.x; r1.w = p3.y;
        float* dst = g_zp + (size_t)n * E_DIM + j0 + tx * 8;
        *(float4*)dst = r0;
        *(float4*)(dst + 4) = r1;

        // C partial for this thread's 8 cols of row n
        float s = r0.x * r0.x;
        s = fmaf(r0.y, r0.y, s);
        s = fmaf(r0.z, r0.z, s);
        s = fmaf(r0.w, r0.w, s);
        s = fmaf(r1.x, r1.x, s);
        s = fmaf(r1.y, r1.y, s);
        s = fmaf(r1.z, r1.z, s);
        s = fmaf(r1.w, r1.w, s);
        // reduce over the 16 tx lanes of this ty (contiguous 16-lane group)
        #pragma unroll
        for (int off = 8; off > 0; off >>= 1)
            s += __shfl_xor_sync(0xffffffffu, s, off);
        if (tx == 0) g_Cp[jb][n] = s;
    }
}

// ============================================================
// Kernel 2: fused distance GEMM + argmin (R9 backbone; changes:
// Ci summed from 4 partials, e2 chunk staged in smem).
// FMA chains identical -> bitwise tokens.
// ============================================================
#define DBM 128
#define DBV 256
#define DBK 16
#define NKT (E_DIM / DBK)          // 32
#define NVT (VCHUNK / DBV)         // 4
#define NT  (NKT * NVT)            // 128

__global__ __launch_bounds__(256, 1) void dist_kernel(
    const float* __restrict__ emb)
{
    __shared__ float As[2][DBK][DBM];
    __shared__ float Bs[2][DBK][DBV];
    __shared__ float sE2[VCHUNK];

    int m0 = blockIdx.x * DBM;
    int chunk = blockIdx.y;
    int vc = chunk * VCHUNK;

    int tid = threadIdx.x;
    int tx  = tid & 15;
    int ty  = tid >> 4;
    int row0 = ty * 8;

    int mA  = tid >> 2;
    int kq4 = (tid & 3) * 4;
    int sw  = kq4 << 1;
    int mAx = mA ^ sw;

    const float* aBase = g_zp + (size_t)(m0 + mA) * E_DIM + kq4;
    const float* bBase = emb  + (size_t)(vc + mA) * E_DIM + kq4;

    float Ci[8];
    #pragma unroll
    for (int i = 0; i < 8; i++) {
        int n = m0 + row0 + i;
        Ci[i] = ((g_Cp[0][n] + g_Cp[1][n]) + g_Cp[2][n]) + g_Cp[3][n];
    }

    float bestv[8];
    int   besti[8];
    #pragma unroll
    for (int i = 0; i < 8; i++) { bestv[i] = 3.4e38f; besti[i] = 0; }

    ull acc[8][8];
    float4 pA0, pA1, pB0, pB1, pB2, pB3;

    #define LOAD_TILE(tt) do {                                              \
        int _k = ((tt) & (NKT - 1)) * DBK;                                  \
        int _v = ((tt) >> 5) * DBV;                                         \
        pA0 = *(const float4*)(aBase + _k);                                 \
        pA1 = *(const float4*)(aBase + (size_t)64 * E_DIM + _k);            \
        const float* _bb = bBase + (size_t)_v * E_DIM + _k;                 \
        pB0 = *(const float4*)(_bb);                                        \
        pB1 = *(const float4*)(_bb + (size_t)64  * E_DIM);                  \
        pB2 = *(const float4*)(_bb + (size_t)128 * E_DIM);                  \
        pB3 = *(const float4*)(_bb + (size_t)192 * E_DIM);                  \
    } while (0)

    #define STS_TILE(bf) do {                                               \
        float* _a = &As[bf][kq4][0];                                        \
        _a[0*DBM + mAx]      = pA0.x; _a[1*DBM + mAx]      = pA0.y;         \
        _a[2*DBM + mAx]      = pA0.z; _a[3*DBM + mAx]      = pA0.w;         \
        _a[0*DBM + mAx + 64] = pA1.x; _a[1*DBM + mAx + 64] = pA1.y;         \
        _a[2*DBM + mAx + 64] = pA1.z; _a[3*DBM + mAx + 64] = pA1.w;         \
        float* _b = &Bs[bf][kq4][0];                                        \
        _b[0*DBV + mAx]       = pB0.x; _b[1*DBV + mAx]       = pB0.y;       \
        _b[2*DBV + mAx]       = pB0.z; _b[3*DBV + mAx]       = pB0.w;       \
        _b[0*DBV + mAx + 64]  = pB1.x; _b[1*DBV + mAx + 64]  = pB1.y;       \
        _b[2*DBV + mAx + 64]  = pB1.z; _b[3*DBV + mAx + 64]  = pB1.w;       \
        _b[0*DBV + mAx + 128] = pB2.x; _b[1*DBV + mAx + 128] = pB2.y;       \
        _b[2*DBV + mAx + 128] = pB2.z; _b[3*DBV + mAx + 128] = pB2.w;       \
        _b[0*DBV + mAx + 192] = pB3.x; _b[1*DBV + mAx + 192] = pB3.y;       \
        _b[2*DBV + mAx + 192] = pB3.z; _b[3*DBV + mAx + 192] = pB3.w;       \
    } while (0)

    #define COMPUTE_KK(bf, kk) do {                                         \
        const int s = ((kk) & 12) << 1;                                     \
        float4 a01 = *(const float4*)&As[bf][kk][(row0 ^ s)];               \
        float4 a23 = *(const float4*)&As[bf][kk][(row0 ^ s) + 4];           \
        ull ad[8];                                                          \
        ad[0] = dup2(a01.x); ad[1] = dup2(a01.y);                           \
        ad[2] = dup2(a01.z); ad[3] = dup2(a01.w);                           \
        ad[4] = dup2(a23.x); ad[5] = dup2(a23.y);                           \
        ad[6] = dup2(a23.z); ad[7] = dup2(a23.w);                           \
        _Pragma("unroll")                                                   \
        for (int g = 0; g < 4; g++) {                                       \
            float4 b = *(const float4*)&Bs[bf][kk][(((g * 16 + tx) * 4) ^ s)]; \
            ull b0 = pack2(b.x, b.y);                                       \
            ull b1 = pack2(b.z, b.w);                                       \
            _Pragma("unroll")                                               \
            for (int i = 0; i < 8; i++) {                                   \
                acc[i][g * 2 + 0] = fma2(ad[i], b0, acc[i][g * 2 + 0]);     \
                acc[i][g * 2 + 1] = fma2(ad[i], b1, acc[i][g * 2 + 1]);     \
            }                                                               \
        }                                                                   \
    } while (0)

    LOAD_TILE(0);
    STS_TILE(0);
    // stage this chunk's e2 into smem (bitwise copies)
    {
        float4 v = *(const float4*)&g_e2[vc + tid * 4];
        *(float4*)&sE2[tid * 4] = v;
    }
    LOAD_TILE(1);
    __syncthreads();

    for (int t = 0; t < NT; t++) {
        int buf = t & 1;

        if ((t & (NKT - 1)) == 0) {
            #pragma unroll
            for (int i = 0; i < 8; i++)
                #pragma unroll
                for (int j = 0; j < 8; j++) acc[i][j] = 0ull;
        }

        #pragma unroll
        for (int kk = 0; kk < DBK / 2; kk++) COMPUTE_KK(buf, kk);

        if (t + 1 < NT) {
            STS_TILE(buf ^ 1);
            int tt = (t + 2 < NT) ? t + 2 : NT - 1;
            LOAD_TILE(tt);
        }

        #pragma unroll
        for (int kk = DBK / 2; kk < DBK; kk++) COMPUTE_KK(buf, kk);

        __syncthreads();

        if ((t & (NKT - 1)) == NKT - 1) {
            int lv0 = (t >> 5) * DBV;
            #pragma unroll
            for (int g = 0; g < 4; g++) {
                int lvb = lv0 + (g * 16 + tx) * 4;
                float4 e4 = *(const float4*)&sE2[lvb];
                int vb = vc + lvb;
                #pragma unroll
                for (int i = 0; i < 8; i++) {
                    float2 p0 = unpack2(acc[i][g * 2 + 0]);
                    float2 p1 = unpack2(acc[i][g * 2 + 1]);
                    float d;
                    d = fmaf(-2.0f, p0.x, Ci[i] + e4.x);
                    if (d < bestv[i]) { bestv[i] = d; besti[i] = vb + 0; }
                    d = fmaf(-2.0f, p0.y, Ci[i] + e4.y);
                    if (d < bestv[i]) { bestv[i] = d; besti[i] = vb + 1; }
                    d = fmaf(-2.0f, p1.x, Ci[i] + e4.z);
                    if (d < bestv[i]) { bestv[i] = d; besti[i] = vb + 2; }
                    d = fmaf(-2.0f, p1.y, Ci[i] + e4.w);
                    if (d < bestv[i]) { bestv[i] = d; besti[i] = vb + 3; }
                }
            }
        }
    }

    #pragma unroll
    for (int i = 0; i < 8; i++) {
        float v = bestv[i];
        int   idx = besti[i];
        #pragma unroll
        for (int off = 8; off > 0; off >>= 1) {
            float ov = __shfl_xor_sync(0xffffffffu, v, off);
            int   oi = __shfl_xor_sync(0xffffffffu, idx, off);
            if (ov < v || (ov == v && oi < idx)) { v = ov; idx = oi; }
        }
        if (tx == 0) {
            int n = m0 + row0 + i;
            g_pv[chunk][n] = v;
            g_pi[chunk][n] = idx;
        }
    }
    #undef LOAD_TILE
    #undef STS_TILE
    #undef COMPUTE_KK
}

// ============================================================
// Kernel 3: pmat split-K: partial P = emb @ post_W over k-range
// [kb*64, kb*64+64).  Bias added in merge.  (z_q tolerance-safe)
// ============================================================
#define BM 64
#define BK 32

__global__ __launch_bounds__(256) void pmat_kernel(
    const float* __restrict__ emb, const float* __restrict__ W)
{
    __shared__ float As2[BK][BM + 4];
    __shared__ float Bs2[BK][64 + 4];

    int m0  = blockIdx.x * BM;
    int kb  = blockIdx.y;
    int tid = threadIdx.x;
    int tx  = tid & 15;
    int ty  = tid >> 4;

    float acc[4][4];
    #pragma unroll
    for (int i = 0; i < 4; i++)
        #pragma unroll
        for (int jj = 0; jj < 4; jj++) acc[i][jj] = 0.f;

    for (int k0 = kb * 64; k0 < kb * 64 + 64; k0 += BK) {
        #pragma unroll
        for (int i = 0; i < 8; i++) {
            int idx = tid + 256 * i;
            int m = idx >> 5, kk = idx & 31;
            As2[kk][m] = emb[(size_t)(m0 + m) * E_DIM + k0 + kk];
        }
        #pragma unroll
        for (int i = 0; i < 8; i++) {
            int idx = tid + 256 * i;
            int kk = idx >> 6, jj = idx & 63;
            Bs2[kk][jj] = W[(size_t)(k0 + kk) * 64 + jj];
        }
        __syncthreads();
        #pragma unroll
        for (int kk = 0; kk < BK; kk++) {
            float a[4], bb[4];
            *(float4*)a  = *(const float4*)&As2[kk][ty * 4];
            *(float4*)bb = *(const float4*)&Bs2[kk][tx * 4];
            #pragma unroll
            for (int i = 0; i < 4; i++)
                #pragma unroll
                for (int jj = 0; jj < 4; jj++)
                    acc[i][jj] = fmaf(a[i], bb[jj], acc[i][jj]);
        }
        __syncthreads();
    }

    #pragma unroll
    for (int i = 0; i < 4; i++) {
        int n = m0 + ty * 4 + i;
        float4 r;
        r.x = acc[i][0];
        r.y = acc[i][1];
        r.z = acc[i][2];
        r.w = acc[i][3];
        *(float4*)&g_Pp[kb][(size_t)n * 64 + tx * 4] = r;
    }
}

// ============================================================
// Kernel 4: merge chunk argmins + write tokens and z_q
// (z_q = bias + sum of pmat partials at tok, ascending kb)
// ============================================================
__global__ __launch_bounds__(256) void merge_gather(
    const float* __restrict__ post_b,
    float* __restrict__ out_tok, float* __restrict__ out_zq)
{
    int n    = blockIdx.x * 8 + (threadIdx.x >> 5);
    int lane = threadIdx.x & 31;

    int tok = 0;
    if (lane == 0) {
        float bv = g_pv[0][n];
        int   bi = g_pi[0][n];
        #pragma unroll
        for (int c = 1; c < NCHUNK; c++) {
            float v = g_pv[c][n];
            int   i = g_pi[c][n];
            if (v < bv) { bv = v; bi = i; }
        }
        tok = bi;
        out_tok[n] = (float)bi;
    }
    tok = __shfl_sync(0xffffffffu, tok, 0);
    if (lane < 16) {
        float4 a = *(const float4*)&post_b[lane * 4];
        #pragma unroll
        for (int kb = 0; kb < PKB; kb++) {
            float4 p = *(const float4*)&g_Pp[kb][(size_t)tok * 64 + lane * 4];
            a.x += p.x; a.y += p.y; a.z += p.z; a.w += p.w;
        }
        *(float4*)&out_zq[(size_t)n * 64 + lane * 4] = a;
    }
}

// ============================================================
extern "C" void kernel_launch(void* const* d_in, const int* in_sizes, int n_in,
                              void* d_out, int out_size)
{
    const float* z      = (const float*)d_in[0];
    const float* emb_W  = (const float*)d_in[1];
    const float* pre_W  = (const float*)d_in[2];
    const float* pre_b  = (const float*)d_in[3];
    const float* post_W = (const float*)d_in[4];
    const float* post_b = (const float*)d_in[5];

    float* out = (float*)d_out;
    float* out_tok = out;
    float* out_zq  = out + N_TOK;

    e2_kernel <<<V_SIZE, 128>>>(emb_W);

    dim3 pgrid(N_TOK / 64, E_DIM / 128);
    pre_gemm  <<<pgrid, 256>>>(z, pre_W, pre_b);

    dim3 mgrid(V_SIZE / BM, PKB);
    pmat_kernel<<<mgrid, 256>>>(emb_W, post_W);

    dim3 dgrid(N_TOK / DBM, NCHUNK);
    dist_kernel<<<dgrid, 256>>>(emb_W);

    merge_gather<<<N_TOK / 8, 256>>>(post_b, out_tok, out_zq);
}

// round 12
// speedup vs baseline: 1.3078x; 1.0264x over previous
#include <cuda_runtime.h>
#include <cstdint>

#define N_TOK   65536
#define K_IN    64
#define E_DIM   512
#define V_SIZE  2048
#define NCHUNK  2
#define VCHUNK  (V_SIZE / NCHUNK)
#define PKB     8                    // pmat split-K factor

typedef unsigned long long ull;

// ---- scratch ----
__device__ float g_zp[(size_t)N_TOK * E_DIM];
__device__ float g_Cp[4][N_TOK];                 // per-j-block |zp|^2 partials
__device__ float g_e2[V_SIZE];
__device__ float g_Pp[PKB][(size_t)V_SIZE * 64]; // pmat k-partials
__device__ float g_pv[NCHUNK][N_TOK];
__device__ int   g_pi[NCHUNK][N_TOK];

// ---- packed fp32x2 helpers (exact IEEE fp32 per lane) ----
__device__ __forceinline__ ull fma2(ull a, ull b, ull c) {
    ull d; asm("fma.rn.f32x2 %0, %1, %2, %3;" : "=l"(d) : "l"(a), "l"(b), "l"(c)); return d;
}
__device__ __forceinline__ ull dup2(float x) {
    ull d; asm("mov.b64 %0, {%1, %1};" : "=l"(d) : "f"(x)); return d;
}
__device__ __forceinline__ ull pack2(float x, float y) {
    ull d; asm("mov.b64 %0, {%1, %2};" : "=l"(d) : "f"(x), "f"(y)); return d;
}
__device__ __forceinline__ float2 unpack2(ull v) {
    float2 r; asm("mov.b64 {%0, %1}, %2;" : "=f"(r.x), "=f"(r.y) : "l"(v)); return r;
}

// ============================================================
// Kernel 0: e2[v] = sum_k emb[v,k]^2   (validated; bitwise path)
// ============================================================
__global__ void e2_kernel(const float* __restrict__ emb) {
    int v = blockIdx.x;
    const float* row = emb + (size_t)v * E_DIM;
    float s = 0.f;
    for (int k = threadIdx.x; k < E_DIM; k += 128) {
        float x = row[k];
        s = fmaf(x, x, s);
    }
    for (int off = 16; off > 0; off >>= 1)
        s += __shfl_down_sync(0xffffffffu, s, off);
    __shared__ float ws[4];
    int lane = threadIdx.x & 31, warp = threadIdx.x >> 5;
    if (lane == 0) ws[warp] = s;
    __syncthreads();
    if (threadIdx.x == 0)
        g_e2[v] = ws[0] + ws[1] + ws[2] + ws[3];
}

// ============================================================
// Kernel 1: tiled pre GEMM + fused C partials (validated R10)
// ============================================================
__global__ __launch_bounds__(256) void pre_gemm(
    const float* __restrict__ z, const float* __restrict__ W,
    const float* __restrict__ b)
{
    __shared__ float As[64][64];
    __shared__ float Ws[64][128];

    int m0 = blockIdx.x * 64;
    int jb = blockIdx.y;
    int j0 = jb * 128;
    int tid = threadIdx.x;
    int tx = tid & 15;
    int ty = tid >> 4;

    #pragma unroll
    for (int l = 0; l < 4; l++) {
        int idx = tid + 256 * l;
        int row = idx >> 4, q = idx & 15;
        float4 v = *(const float4*)(z + (size_t)(m0 + row) * K_IN + q * 4);
        *(float4*)&As[row][q * 4] = v;
    }
    #pragma unroll
    for (int l = 0; l < 8; l++) {
        int idx = tid + 256 * l;
        int row = idx >> 5, q = idx & 31;
        float4 v = *(const float4*)(W + (size_t)row * E_DIM + j0 + q * 4);
        *(float4*)&Ws[row][q * 4] = v;
    }
    __syncthreads();

    float4 bl0 = *(const float4*)&b[j0 + tx * 8];
    float4 bl1 = *(const float4*)&b[j0 + tx * 8 + 4];
    ull acc[4][4];
    #pragma unroll
    for (int i = 0; i < 4; i++) {
        acc[i][0] = pack2(bl0.x, bl0.y);
        acc[i][1] = pack2(bl0.z, bl0.w);
        acc[i][2] = pack2(bl1.x, bl1.y);
        acc[i][3] = pack2(bl1.z, bl1.w);
    }

    #pragma unroll 8
    for (int kk = 0; kk < K_IN; kk++) {
        float a0 = As[ty * 4 + 0][kk];
        float a1 = As[ty * 4 + 1][kk];
        float a2 = As[ty * 4 + 2][kk];
        float a3 = As[ty * 4 + 3][kk];
        float4 w0 = *(const float4*)&Ws[kk][tx * 8];
        float4 w1 = *(const float4*)&Ws[kk][tx * 8 + 4];
        ull b0 = pack2(w0.x, w0.y), b1 = pack2(w0.z, w0.w);
        ull b2 = pack2(w1.x, w1.y), b3 = pack2(w1.z, w1.w);
        ull ad0 = dup2(a0), ad1 = dup2(a1), ad2 = dup2(a2), ad3 = dup2(a3);
        acc[0][0] = fma2(ad0, b0, acc[0][0]); acc[0][1] = fma2(ad0, b1, acc[0][1]);
        acc[0][2] = fma2(ad0, b2, acc[0][2]); acc[0][3] = fma2(ad0, b3, acc[0][3]);
        acc[1][0] = fma2(ad1, b0, acc[1][0]); acc[1][1] = fma2(ad1, b1, acc[1][1]);
        acc[1][2] = fma2(ad1, b2, acc[1][2]); acc[1][3] = fma2(ad1, b3, acc[1][3]);
        acc[2][0] = fma2(ad2, b0, acc[2][0]); acc[2][1] = fma2(ad2, b1, acc[2][1]);
        acc[2][2] = fma2(ad2, b2, acc[2][2]); acc[2][3] = fma2(ad2, b3, acc[2][3]);
        acc[3][0] = fma2(ad3, b0, acc[3][0]); acc[3][1] = fma2(ad3, b1, acc[3][1]);
        acc[3][2] = fma2(ad3, b2, acc[3][2]); acc[3][3] = fma2(ad3, b3, acc[3][3]);
    }

    #pragma unroll
    for (int i = 0; i < 4; i++) {
        int n = m0 + ty * 4 + i;
        float2 p0 = unpack2(acc[i][0]), p1 = unpack2(acc[i][1]);
        float2 p2 = unpack2(acc[i][2]), p3 = unpack2(acc[i][3]);
        float4 r0; r0.x = p0.x; r0.y = p0.y; r0.z = p1.x; r0.w = p1.y;
        float4 r1; r1.x = p2.x; r1.y = p2.y; r1.z = p3.x; r1.w = p3.y;
        float* dst = g_zp + (size_t)n * E_DIM + j0 + tx * 8;
        *(float4*)dst = r0;
        *(float4*)(dst + 4) = r1;

        float s = r0.x * r0.x;
        s = fmaf(r0.y, r0.y, s);
        s = fmaf(r0.z, r0.z, s);
        s = fmaf(r0.w, r0.w, s);
        s = fmaf(r1.x, r1.x, s);
        s = fmaf(r1.y, r1.y, s);
        s = fmaf(r1.z, r1.z, s);
        s = fmaf(r1.w, r1.w, s);
        #pragma unroll
        for (int off = 8; off > 0; off >>= 1)
            s += __shfl_xor_sync(0xffffffffu, s, off);
        if (tx == 0) g_Cp[jb][n] = s;
    }
}

// ============================================================
// Kernel 2: fused distance GEMM + argmin.  R10 backbone; change:
// LSU work spread through the kk loop in three slices
// (STS A+B01 after kk=3, STS B23 after kk=7, LDG t+2 after
// kk=11) instead of one burst. FMA chains identical -> bitwise.
// ============================================================
#define DBM 128
#define DBV 256
#define DBK 16
#define NKT (E_DIM / DBK)          // 32
#define NVT (VCHUNK / DBV)         // 4
#define NT  (NKT * NVT)            // 128

__global__ __launch_bounds__(256, 1) void dist_kernel(
    const float* __restrict__ emb)
{
    __shared__ float As[2][DBK][DBM];
    __shared__ float Bs[2][DBK][DBV];
    __shared__ float sE2[VCHUNK];

    int m0 = blockIdx.x * DBM;
    int chunk = blockIdx.y;
    int vc = chunk * VCHUNK;

    int tid = threadIdx.x;
    int tx  = tid & 15;
    int ty  = tid >> 4;
    int row0 = ty * 8;

    int mA  = tid >> 2;
    int kq4 = (tid & 3) * 4;
    int sw  = kq4 << 1;
    int mAx = mA ^ sw;

    const float* aBase = g_zp + (size_t)(m0 + mA) * E_DIM + kq4;
    const float* bBase = emb  + (size_t)(vc + mA) * E_DIM + kq4;

    float Ci[8];
    #pragma unroll
    for (int i = 0; i < 8; i++) {
        int n = m0 + row0 + i;
        Ci[i] = ((g_Cp[0][n] + g_Cp[1][n]) + g_Cp[2][n]) + g_Cp[3][n];
    }

    float bestv[8];
    int   besti[8];
    #pragma unroll
    for (int i = 0; i < 8; i++) { bestv[i] = 3.4e38f; besti[i] = 0; }

    ull acc[8][8];
    float4 pA0, pA1, pB0, pB1, pB2, pB3;

    #define LOAD_TILE(tt) do {                                              \
        int _k = ((tt) & (NKT - 1)) * DBK;                                  \
        int _v = ((tt) >> 5) * DBV;                                         \
        pA0 = *(const float4*)(aBase + _k);                                 \
        pA1 = *(const float4*)(aBase + (size_t)64 * E_DIM + _k);            \
        const float* _bb = bBase + (size_t)_v * E_DIM + _k;                 \
        pB0 = *(const float4*)(_bb);                                        \
        pB1 = *(const float4*)(_bb + (size_t)64  * E_DIM);                  \
        pB2 = *(const float4*)(_bb + (size_t)128 * E_DIM);                  \
        pB3 = *(const float4*)(_bb + (size_t)192 * E_DIM);                  \
    } while (0)

    #define STS_A_B01(bf) do {                                              \
        float* _a = &As[bf][kq4][0];                                        \
        _a[0*DBM + mAx]      = pA0.x; _a[1*DBM + mAx]      = pA0.y;         \
        _a[2*DBM + mAx]      = pA0.z; _a[3*DBM + mAx]      = pA0.w;         \
        _a[0*DBM + mAx + 64] = pA1.x; _a[1*DBM + mAx + 64] = pA1.y;         \
        _a[2*DBM + mAx + 64] = pA1.z; _a[3*DBM + mAx + 64] = pA1.w;         \
        float* _b = &Bs[bf][kq4][0];                                        \
        _b[0*DBV + mAx]       = pB0.x; _b[1*DBV + mAx]       = pB0.y;       \
        _b[2*DBV + mAx]       = pB0.z; _b[3*DBV + mAx]       = pB0.w;       \
        _b[0*DBV + mAx + 64]  = pB1.x; _b[1*DBV + mAx + 64]  = pB1.y;       \
        _b[2*DBV + mAx + 64]  = pB1.z; _b[3*DBV + mAx + 64]  = pB1.w;       \
    } while (0)

    #define STS_B23(bf) do {                                                \
        float* _b = &Bs[bf][kq4][0];                                        \
        _b[0*DBV + mAx + 128] = pB2.x; _b[1*DBV + mAx + 128] = pB2.y;       \
        _b[2*DBV + mAx + 128] = pB2.z; _b[3*DBV + mAx + 128] = pB2.w;       \
        _b[0*DBV + mAx + 192] = pB3.x; _b[1*DBV + mAx + 192] = pB3.y;       \
        _b[2*DBV + mAx + 192] = pB3.z; _b[3*DBV + mAx + 192] = pB3.w;       \
    } while (0)

    #define COMPUTE_KK(bf, kk) do {                                         \
        const int s = ((kk) & 12) << 1;                                     \
        float4 a01 = *(const float4*)&As[bf][kk][(row0 ^ s)];               \
        float4 a23 = *(const float4*)&As[bf][kk][(row0 ^ s) + 4];           \
        ull ad[8];                                                          \
        ad[0] = dup2(a01.x); ad[1] = dup2(a01.y);                           \
        ad[2] = dup2(a01.z); ad[3] = dup2(a01.w);                           \
        ad[4] = dup2(a23.x); ad[5] = dup2(a23.y);                           \
        ad[6] = dup2(a23.z); ad[7] = dup2(a23.w);                           \
        _Pragma("unroll")                                                   \
        for (int g = 0; g < 4; g++) {                                       \
            float4 b = *(const float4*)&Bs[bf][kk][(((g * 16 + tx) * 4) ^ s)]; \
            ull b0 = pack2(b.x, b.y);                                       \
            ull b1 = pack2(b.z, b.w);                                       \
            _Pragma("unroll")                                               \
            for (int i = 0; i < 8; i++) {                                   \
                acc[i][g * 2 + 0] = fma2(ad[i], b0, acc[i][g * 2 + 0]);     \
                acc[i][g * 2 + 1] = fma2(ad[i], b1, acc[i][g * 2 + 1]);     \
            }                                                               \
        }                                                                   \
    } while (0)

    LOAD_TILE(0);
    STS_A_B01(0);
    STS_B23(0);
    {
        float4 v = *(const float4*)&g_e2[vc + tid * 4];
        *(float4*)&sE2[tid * 4] = v;
    }
    LOAD_TILE(1);
    __syncthreads();

    for (int t = 0; t < NT; t++) {
        int buf = t & 1;
        bool more = (t + 1 < NT);

        if ((t & (NKT - 1)) == 0) {
            #pragma unroll
            for (int i = 0; i < 8; i++)
                #pragma unroll
                for (int j = 0; j < 8; j++) acc[i][j] = 0ull;
        }

        #pragma unroll
        for (int kk = 0; kk < 4; kk++) COMPUTE_KK(buf, kk);

        if (more) STS_A_B01(buf ^ 1);          // regs hold tile t+1

        #pragma unroll
        for (int kk = 4; kk < 8; kk++) COMPUTE_KK(buf, kk);

        if (more) STS_B23(buf ^ 1);

        #pragma unroll
        for (int kk = 8; kk < 12; kk++) COMPUTE_KK(buf, kk);

        if (more) {                             // all STS done: safe to clobber
            int tt = (t + 2 < NT) ? t + 2 : NT - 1;
            LOAD_TILE(tt);
        }

        #pragma unroll
        for (int kk = 12; kk < DBK; kk++) COMPUTE_KK(buf, kk);

        __syncthreads();

        if ((t & (NKT - 1)) == NKT - 1) {
            int lv0 = (t >> 5) * DBV;
            #pragma unroll
            for (int g = 0; g < 4; g++) {
                int lvb = lv0 + (g * 16 + tx) * 4;
                float4 e4 = *(const float4*)&sE2[lvb];
                int vb = vc + lvb;
                #pragma unroll
                for (int i = 0; i < 8; i++) {
                    float2 p0 = unpack2(acc[i][g * 2 + 0]);
                    float2 p1 = unpack2(acc[i][g * 2 + 1]);
                    float d;
                    d = fmaf(-2.0f, p0.x, Ci[i] + e4.x);
                    if (d < bestv[i]) { bestv[i] = d; besti[i] = vb + 0; }
                    d = fmaf(-2.0f, p0.y, Ci[i] + e4.y);
                    if (d < bestv[i]) { bestv[i] = d; besti[i] = vb + 1; }
                    d = fmaf(-2.0f, p1.x, Ci[i] + e4.z);
                    if (d < bestv[i]) { bestv[i] = d; besti[i] = vb + 2; }
                    d = fmaf(-2.0f, p1.y, Ci[i] + e4.w);
                    if (d < bestv[i]) { bestv[i] = d; besti[i] = vb + 3; }
                }
            }
        }
    }

    #pragma unroll
    for (int i = 0; i < 8; i++) {
        float v = bestv[i];
        int   idx = besti[i];
        #pragma unroll
        for (int off = 8; off > 0; off >>= 1) {
            float ov = __shfl_xor_sync(0xffffffffu, v, off);
            int   oi = __shfl_xor_sync(0xffffffffu, idx, off);
            if (ov < v || (ov == v && oi < idx)) { v = ov; idx = oi; }
        }
        if (tx == 0) {
            int n = m0 + row0 + i;
            g_pv[chunk][n] = v;
            g_pi[chunk][n] = idx;
        }
    }
    #undef LOAD_TILE
    #undef STS_A_B01
    #undef STS_B23
    #undef COMPUTE_KK
}

// ============================================================
// Kernel 3: pmat split-K (validated R10)
// ============================================================
#define BM 64
#define BK 32

__global__ __launch_bounds__(256) void pmat_kernel(
    const float* __restrict__ emb, const float* __restrict__ W)
{
    __shared__ float As2[BK][BM + 4];
    __shared__ float Bs2[BK][64 + 4];

    int m0  = blockIdx.x * BM;
    int kb  = blockIdx.y;
    int tid = threadIdx.x;
    int tx  = tid & 15;
    int ty  = tid >> 4;

    float acc[4][4];
    #pragma unroll
    for (int i = 0; i < 4; i++)
        #pragma unroll
        for (int jj = 0; jj < 4; jj++) acc[i][jj] = 0.f;

    for (int k0 = kb * 64; k0 < kb * 64 + 64; k0 += BK) {
        #pragma unroll
        for (int i = 0; i < 8; i++) {
            int idx = tid + 256 * i;
            int m = idx >> 5, kk = idx & 31;
            As2[kk][m] = emb[(size_t)(m0 + m) * E_DIM + k0 + kk];
        }
        #pragma unroll
        for (int i = 0; i < 8; i++) {
            int idx = tid + 256 * i;
            int kk = idx >> 6, jj = idx & 63;
            Bs2[kk][jj] = W[(size_t)(k0 + kk) * 64 + jj];
        }
        __syncthreads();
        #pragma unroll
        for (int kk = 0; kk < BK; kk++) {
            float a[4], bb[4];
            *(float4*)a  = *(const float4*)&As2[kk][ty * 4];
            *(float4*)bb = *(const float4*)&Bs2[kk][tx * 4];
            #pragma unroll
            for (int i = 0; i < 4; i++)
                #pragma unroll
                for (int jj = 0; jj < 4; jj++)
                    acc[i][jj] = fmaf(a[i], bb[jj], acc[i][jj]);
        }
        __syncthreads();
    }

    #pragma unroll
    for (int i = 0; i < 4; i++) {
        int n = m0 + ty * 4 + i;
        float4 r;
        r.x = acc[i][0];
        r.y = acc[i][1];
        r.z = acc[i][2];
        r.w = acc[i][3];
        *(float4*)&g_Pp[kb][(size_t)n * 64 + tx * 4] = r;
    }
}

// ============================================================
// Kernel 4: merge chunk argmins + write tokens and z_q
// ============================================================
__global__ __launch_bounds__(256) void merge_gather(
    const float* __restrict__ post_b,
    float* __restrict__ out_tok, float* __restrict__ out_zq)
{
    int n    = blockIdx.x * 8 + (threadIdx.x >> 5);
    int lane = threadIdx.x & 31;

    int tok = 0;
    if (lane == 0) {
        float bv = g_pv[0][n];
        int   bi = g_pi[0][n];
        #pragma unroll
        for (int c = 1; c < NCHUNK; c++) {
            float v = g_pv[c][n];
            int   i = g_pi[c][n];
            if (v < bv) { bv = v; bi = i; }
        }
        tok = bi;
        out_tok[n] = (float)bi;
    }
    tok = __shfl_sync(0xffffffffu, tok, 0);
    if (lane < 16) {
        float4 a = *(const float4*)&post_b[lane * 4];
        #pragma unroll
        for (int kb = 0; kb < PKB; kb++) {
            float4 p = *(const float4*)&g_Pp[kb][(size_t)tok * 64 + lane * 4];
            a.x += p.x; a.y += p.y; a.z += p.z; a.w += p.w;
        }
        *(float4*)&out_zq[(size_t)n * 64 + lane * 4] = a;
    }
}

// ============================================================
extern "C" void kernel_launch(void* const* d_in, const int* in_sizes, int n_in,
                              void* d_out, int out_size)
{
    const float* z      = (const float*)d_in[0];
    const float* emb_W  = (const float*)d_in[1];
    const float* pre_W  = (const float*)d_in[2];
    const float* pre_b  = (const float*)d_in[3];
    const float* post_W = (const float*)d_in[4];
    const float* post_b = (const float*)d_in[5];

    float* out = (float*)d_out;
    float* out_tok = out;
    float* out_zq  = out + N_TOK;

    e2_kernel <<<V_SIZE, 128>>>(emb_W);

    dim3 pgrid(N_TOK / 64, E_DIM / 128);
    pre_gemm  <<<pgrid, 256>>>(z, pre_W, pre_b);

    dim3 mgrid(V_SIZE / BM, PKB);
    pmat_kernel<<<mgrid, 256>>>(emb_W, post_W);

    dim3 dgrid(N_TOK / DBM, NCHUNK);
    dist_kernel<<<dgrid, 256>>>(emb_W);

    merge_gather<<<N_TOK / 8, 256>>>(post_b, out_tok, out_zq);
}